// round 8
// baseline (speedup 1.0000x reference)
#include <cuda_runtime.h>
#include <cstdint>

typedef unsigned int u32;

#define BATCH 16
#define DIM   256
#define HW    1024
#define HEADS 4

// Scratch (allocation-free rule: __device__ globals)
__device__ float g_an[BATCH * DIM * HW];   // [b][c][q]  (tf32-rounded)
__device__ float g_bn[BATCH * DIM * HW];   // [b][c][q]  (tf32-rounded)
__device__ float g_q [BATCH * DIM * HW];   // [bh][q][d] (x 1/16, tf32-rounded)
__device__ float g_k [BATCH * DIM * HW];   // [bh][d][q] (tf32-rounded)
__device__ float g_v [BATCH * DIM * HW];   // [bh][q][d] (tf32-rounded)
__device__ float g_h [BATCH * DIM * HW];   // [b][c][q]  (tf32-rounded)
__device__ float g_w [4 * DIM * DIM];      // rounded Wq,Wk,Wv,Wp

// ---------------------------------------------------------------------------
// Helpers
// ---------------------------------------------------------------------------
__device__ __forceinline__ void mma_tf32(float* d, const u32* a, const u32* b) {
    asm volatile(
        "mma.sync.aligned.m16n8k8.row.col.f32.tf32.tf32.f32 "
        "{%0,%1,%2,%3}, {%4,%5,%6,%7}, {%8,%9}, {%0,%1,%2,%3};"
        : "+f"(d[0]), "+f"(d[1]), "+f"(d[2]), "+f"(d[3])
        : "r"(a[0]), "r"(a[1]), "r"(a[2]), "r"(a[3]), "r"(b[0]), "r"(b[1]));
}
__device__ __forceinline__ u32 to_tf32(float f) {
    u32 r; asm("cvt.rna.tf32.f32 %0, %1;" : "=r"(r) : "f"(f)); return r;
}
__device__ __forceinline__ float rndf(float f) { return __uint_as_float(to_tf32(f)); }
__device__ __forceinline__ u32 smem_u32(const void* p) {
    u32 a;
    asm("{ .reg .u64 t; cvta.to.shared.u64 t, %1; cvt.u32.u64 %0, t; }" : "=r"(a) : "l"(p));
    return a;
}
__device__ __forceinline__ void cp16(u32 dst, const float* src) {
    asm volatile("cp.async.cg.shared.global [%0], [%1], 16;" :: "r"(dst), "l"(src));
}
#define CP_COMMIT() asm volatile("cp.async.commit_group;")
#define CP_WAIT0()  asm volatile("cp.async.wait_group 0;")
#define CP_WAIT1()  asm volatile("cp.async.wait_group 1;")

__inline__ __device__ float warpReduceSum(float v) {
    #pragma unroll
    for (int o = 16; o > 0; o >>= 1) v += __shfl_down_sync(0xffffffffu, v, o);
    return v;
}

// ---------------------------------------------------------------------------
// Weight pre-rounding: g_w[y] = rna_tf32(W_y)
// ---------------------------------------------------------------------------
__global__ __launch_bounds__(256)
void wconv_kernel(const float* __restrict__ w0, const float* __restrict__ w1,
                  const float* __restrict__ w2, const float* __restrict__ w3,
                  float* __restrict__ out) {
    const float* s = (blockIdx.y == 0) ? w0 : (blockIdx.y == 1) ? w1
                   : (blockIdx.y == 2) ? w2 : w3;
    int i = (blockIdx.x * 256 + threadIdx.x) * 4;
    float4 v = *(const float4*)(s + i);
    v.x = rndf(v.x); v.y = rndf(v.y); v.z = rndf(v.z); v.w = rndf(v.w);
    *(float4*)(out + (size_t)blockIdx.y * DIM * DIM + i) = v;
}

// ---------------------------------------------------------------------------
// GroupNorm (both tensors in one launch; z selects). [b][c][q] -> [b][c][q].
// ---------------------------------------------------------------------------
__global__ __launch_bounds__(256)
void gn_kernel(const float* __restrict__ xa, const float* __restrict__ xb,
               const float* __restrict__ gwA, const float* __restrict__ gbA,
               const float* __restrict__ gwB, const float* __restrict__ gbB,
               float* __restrict__ ya, float* __restrict__ yb) {
    const int g = blockIdx.x, b = blockIdx.y, t = threadIdx.x;
    const int which = blockIdx.z;
    const float* x = which ? xb : xa;
    const float* gamma = which ? gwB : gwA;
    const float* beta  = which ? gbB : gbA;
    float* y = which ? yb : ya;

    const int base = (b * DIM + g * 8) * HW;
    const float4* xp = (const float4*)(x + base);
    float4* yp = (float4*)(y + base);

    float4 r[8];
    float s = 0.f, s2 = 0.f;
    #pragma unroll
    for (int k = 0; k < 8; k++) {
        float4 v = xp[k * 256 + t];
        r[k] = v;
        s  += (v.x + v.y) + (v.z + v.w);
        s2 += (v.x * v.x + v.y * v.y) + (v.z * v.z + v.w * v.w);
    }
    s = warpReduceSum(s); s2 = warpReduceSum(s2);

    __shared__ float sh[2][8];
    int w = t >> 5, lane = t & 31;
    if (lane == 0) { sh[0][w] = s; sh[1][w] = s2; }
    __syncthreads();
    __shared__ float mu_s, inv_s;
    if (t == 0) {
        float S = 0.f, S2 = 0.f;
        #pragma unroll
        for (int i = 0; i < 8; i++) { S += sh[0][i]; S2 += sh[1][i]; }
        float mu = S * (1.0f / 8192.0f);
        float var = S2 * (1.0f / 8192.0f) - mu * mu;
        mu_s = mu; inv_s = rsqrtf(var + 1e-6f);
    }
    __syncthreads();
    const float mu = mu_s, inv = inv_s;

    #pragma unroll
    for (int k = 0; k < 8; k++) {
        int c = g * 8 + ((k * 256 + t) >> 8);
        float sc = inv * gamma[c];
        float shf = beta[c] - mu * sc;
        float4 v = r[k];
        v.x = rndf(v.x * sc + shf); v.y = rndf(v.y * sc + shf);
        v.z = rndf(v.z * sc + shf); v.w = rndf(v.w * sc + shf);
        yp[k * 256 + t] = v;
    }
}

// ---------------------------------------------------------------------------
// Shared GEMM core pieces (mma.sync tf32, cp.async staging).
// CTA tile M=128 x N=128, K=256 in 8 chunks of 32. 8 warps = 2(m) x 4(n).
// Smem: Ws[m][k] stride 36, Xs[k][n] stride 136 (conflict-free frags).
// ---------------------------------------------------------------------------
struct ProjCtx {
    u32 smb;
    int tid, wid, lane, r4, c4, wm, wn;
};

__device__ __forceinline__ void proj_stage(const ProjCtx& cx, int ch,
                                           const float* W, const float* Xb,
                                           int m0, int n0) {
    const int k0 = ch * 32;
    const u32 wd = cx.smb + (u32)((ch & 1) ? 128 * 36 * 4 : 0);
    const u32 xd = cx.smb + (u32)(2 * 128 * 36 * 4 + ((ch & 1) ? 32 * 136 * 4 : 0));
    #pragma unroll
    for (int r = 0; r < 4; r++) {
        int idx = r * 256 + cx.tid;
        int row = idx >> 3, col = (idx & 7) << 2;
        cp16(wd + (u32)(row * 36 + col) * 4, W + (size_t)(m0 + row) * DIM + k0 + col);
    }
    #pragma unroll
    for (int r = 0; r < 4; r++) {
        int idx = r * 256 + cx.tid;
        int row = idx >> 5, col = (idx & 31) << 2;
        cp16(xd + (u32)(row * 136 + col) * 4, Xb + (size_t)(k0 + row) * HW + n0 + col);
    }
    CP_COMMIT();
}

__device__ __forceinline__ void proj_mainloop(const ProjCtx& cx, const u32* dsm,
                                              const float* W, const float* Xb,
                                              int m0, int n0, float d[4][4][4]) {
    proj_stage(cx, 0, W, Xb, m0, n0);
    for (int ch = 0; ch < 8; ch++) {
        if (ch < 7) { proj_stage(cx, ch + 1, W, Xb, m0, n0); CP_WAIT1(); } else { CP_WAIT0(); }
        __syncthreads();
        const u32* Ws = dsm + ((ch & 1) ? 128 * 36 : 0);
        const u32* Xs = dsm + 2 * 128 * 36 + ((ch & 1) ? 32 * 136 : 0);
        #pragma unroll
        for (int k8 = 0; k8 < 4; k8++) {
            u32 a[4][4], bb[4][2];
            #pragma unroll
            for (int i = 0; i < 4; i++) {
                const u32* p = Ws + (cx.wm * 64 + 16 * i) * 36 + k8 * 8;
                a[i][0] = p[cx.r4 * 36 + cx.c4];
                a[i][1] = p[(cx.r4 + 8) * 36 + cx.c4];
                a[i][2] = p[cx.r4 * 36 + cx.c4 + 4];
                a[i][3] = p[(cx.r4 + 8) * 36 + cx.c4 + 4];
            }
            #pragma unroll
            for (int j = 0; j < 4; j++) {
                const u32* p = Xs + k8 * 8 * 136 + cx.wn * 32 + 8 * j + cx.r4;
                bb[j][0] = p[cx.c4 * 136];
                bb[j][1] = p[(cx.c4 + 4) * 136];
            }
            #pragma unroll
            for (int i = 0; i < 4; i++)
                #pragma unroll
                for (int j = 0; j < 4; j++)
                    mma_tf32(d[i][j], a[i], bb[j]);
        }
        __syncthreads();
    }
}

// ---------------------------------------------------------------------------
// QKV projection, one launch: z = proj*16 + b.  proj 0 = Q (x = bn, scale
// 1/16, out [bh][q][d]), 1 = K (out [bh][d][q]), 2 = V (out [bh][q][d]).
// ---------------------------------------------------------------------------
__global__ __launch_bounds__(256, 2)
void qkv_kernel(const float* __restrict__ wbuf,
                const float* __restrict__ an, const float* __restrict__ bn,
                const float* __restrict__ bq, const float* __restrict__ bk,
                const float* __restrict__ bv,
                float* __restrict__ Yq, float* __restrict__ Yk, float* __restrict__ Yv) {
    extern __shared__ u32 dsm[];
    ProjCtx cx;
    cx.smb = smem_u32(dsm);
    cx.tid = threadIdx.x; cx.wid = cx.tid >> 5; cx.lane = cx.tid & 31;
    cx.r4 = cx.lane >> 2; cx.c4 = cx.lane & 3;
    cx.wm = cx.wid >> 2; cx.wn = cx.wid & 3;

    const int pz = blockIdx.z >> 4;        // 0=Q 1=K 2=V
    const int b  = blockIdx.z & 15;
    const int n0 = blockIdx.x * 128, m0 = blockIdx.y * 128;
    const float* W  = wbuf + (size_t)pz * DIM * DIM;
    const float* Xb = ((pz == 0) ? bn : an) + (size_t)b * DIM * HW;
    const float* bias = (pz == 0) ? bq : (pz == 1) ? bk : bv;
    float* Y = (pz == 0) ? Yq : (pz == 1) ? Yk : Yv;

    float d[4][4][4];
    #pragma unroll
    for (int i = 0; i < 4; i++)
        #pragma unroll
        for (int j = 0; j < 4; j++)
            #pragma unroll
            for (int e = 0; e < 4; e++) d[i][j][e] = 0.f;

    proj_mainloop(cx, dsm, W, Xb, m0, n0, d);

    const float sc = (pz == 0) ? 0.0625f : 1.0f;
    #pragma unroll
    for (int i = 0; i < 4; i++) {
        #pragma unroll
        for (int half = 0; half < 2; half++) {
            const int m = m0 + cx.wm * 64 + 16 * i + cx.r4 + 8 * half;
            const float bvv = bias[m];
            const int hh = m >> 6, dd = m & 63;
            if (pz == 1) {
                float* Yh = Y + ((size_t)(b * HEADS + hh) << 16) + (size_t)dd * HW;
                #pragma unroll
                for (int j = 0; j < 4; j++) {
                    const int n = n0 + cx.wn * 32 + 8 * j + 2 * cx.c4;
                    float2 v = make_float2(rndf(d[i][j][2 * half] + bvv),
                                           rndf(d[i][j][2 * half + 1] + bvv));
                    *(float2*)(Yh + n) = v;
                }
            } else {
                float* Yh = Y + ((size_t)(b * HEADS + hh) << 16) + dd;
                #pragma unroll
                for (int j = 0; j < 4; j++) {
                    const int n = n0 + cx.wn * 32 + 8 * j + 2 * cx.c4;
                    Yh[(size_t)n * 64]       = rndf((d[i][j][2 * half] + bvv) * sc);
                    Yh[(size_t)(n + 1) * 64] = rndf((d[i][j][2 * half + 1] + bvv) * sc);
                }
            }
        }
    }
}

// ---------------------------------------------------------------------------
// Final projection: out[b][m][q] = (Wp @ h + bias + skip) / sqrt(2)
// ---------------------------------------------------------------------------
__global__ __launch_bounds__(256, 2)
void final_kernel(const float* __restrict__ W, const float* __restrict__ X,
                  const float* __restrict__ bias, const float* __restrict__ skip,
                  float* __restrict__ Y) {
    extern __shared__ u32 dsm[];
    ProjCtx cx;
    cx.smb = smem_u32(dsm);
    cx.tid = threadIdx.x; cx.wid = cx.tid >> 5; cx.lane = cx.tid & 31;
    cx.r4 = cx.lane >> 2; cx.c4 = cx.lane & 3;
    cx.wm = cx.wid >> 2; cx.wn = cx.wid & 3;

    const int n0 = blockIdx.x * 128, m0 = blockIdx.y * 128, b = blockIdx.z;
    const float* Xb = X + (size_t)b * DIM * HW;

    float d[4][4][4];
    #pragma unroll
    for (int i = 0; i < 4; i++)
        #pragma unroll
        for (int j = 0; j < 4; j++)
            #pragma unroll
            for (int e = 0; e < 4; e++) d[i][j][e] = 0.f;

    proj_mainloop(cx, dsm, W, Xb, m0, n0, d);

    const float r2 = 0.7071067811865476f;
    #pragma unroll
    for (int i = 0; i < 4; i++) {
        #pragma unroll
        for (int half = 0; half < 2; half++) {
            const int m = m0 + cx.wm * 64 + 16 * i + cx.r4 + 8 * half;
            const float bvv = bias[m];
            const size_t rowb = ((size_t)b * DIM + m) * HW;
            #pragma unroll
            for (int j = 0; j < 4; j++) {
                const int n = n0 + cx.wn * 32 + 8 * j + 2 * cx.c4;
                float2 sk = *(const float2*)(skip + rowb + n);
                float2 v = make_float2((d[i][j][2 * half] + bvv + sk.x) * r2,
                                       (d[i][j][2 * half + 1] + bvv + sk.y) * r2);
                *(float2*)(Y + rowb + n) = v;
            }
        }
    }
}

// ---------------------------------------------------------------------------
// Attention (mma.sync tf32, double-buffered cp.async). CTA = (64 q, head, b),
// 256 threads = 8 warps (2 m x 4 n). 16 key-chunks of 64:
//   wait(ch) -> sync -> issue stage(ch+1) -> S = Q@K^T -> exp -> Ps -> sync
//   -> O += P@V.   2 syncs/chunk; staging overlaps full chunk compute.
// Smem: Qs[64][68], Ps[64][68], Ks[2][64][72] ([d][key]), Vs[2][64][72]
// ([key][d]) = 108,544 B -> occupancy 2.
// ---------------------------------------------------------------------------
__global__ __launch_bounds__(256, 2)
void attn_kernel(const float* __restrict__ Qg, const float* __restrict__ Kg,
                 const float* __restrict__ Vg, float* __restrict__ O) {
    extern __shared__ u32 dsm[];
    u32* Qs = dsm;                        // 64 x 68
    u32* Ps = Qs + 64 * 68;               // 64 x 68
    u32* Ksb = Ps + 64 * 68;              // 2 x 64 x 72
    u32* Vsb = Ksb + 2 * 64 * 72;         // 2 x 64 x 72
    __shared__ float Lsum[64];
    const u32 smb = smem_u32(dsm);
    const u32 QsA = smb;
    const u32 KsA = smb + (2 * 64 * 68) * 4;
    const u32 VsA = KsA + (2 * 64 * 72) * 4;

    const int tid = threadIdx.x;
    const int wid = tid >> 5, lane = tid & 31;
    const int r4 = lane >> 2, c4 = lane & 3;
    const int wm = wid >> 2, wn = wid & 3;
    const int q0 = blockIdx.x * 64;
    const int h = blockIdx.y, b = blockIdx.z;
    const int bh = b * HEADS + h;
    const float* Qb = Qg + ((size_t)bh << 16);   // [q][d]
    const float* Kb = Kg + ((size_t)bh << 16);   // [d][key]
    const float* Vb = Vg + ((size_t)bh << 16);   // [key][d]

    // stage K/V chunk ch into buffer ch&1 (4 cp16 each per thread)
    auto stageKV = [&](int ch) {
        const int kb = ch * 64;
        const u32 kd = KsA + (u32)((ch & 1) * 64 * 72 * 4);
        const u32 vd = VsA + (u32)((ch & 1) * 64 * 72 * 4);
        #pragma unroll
        for (int r = 0; r < 4; r++) {
            int idx = r * 256 + tid;
            int row = idx >> 4, col = (idx & 15) << 2;
            cp16(kd + (u32)(row * 72 + col) * 4, Kb + (size_t)row * HW + kb + col);
            cp16(vd + (u32)(row * 72 + col) * 4, Vb + (size_t)(kb + row) * 64 + col);
        }
        CP_COMMIT();
    };

    // prologue: Q (once) + chunk 0, one group
    #pragma unroll
    for (int r = 0; r < 4; r++) {
        int idx = r * 256 + tid;
        int row = idx >> 4, col = (idx & 15) << 2;
        cp16(QsA + (u32)(row * 68 + col) * 4, Qb + (size_t)(q0 + row) * 64 + col);
    }
    {
        const u32 kd = KsA, vd = VsA;
        #pragma unroll
        for (int r = 0; r < 4; r++) {
            int idx = r * 256 + tid;
            int row = idx >> 4, col = (idx & 15) << 2;
            cp16(kd + (u32)(row * 72 + col) * 4, Kb + (size_t)row * HW + col);
            cp16(vd + (u32)(row * 72 + col) * 4, Vb + (size_t)row * 64 + col);
        }
        CP_COMMIT();
    }
    if (tid < 64) Lsum[tid] = 0.f;

    float o[2][2][4];
    #pragma unroll
    for (int i = 0; i < 2; i++)
        #pragma unroll
        for (int j = 0; j < 2; j++)
            #pragma unroll
            for (int e = 0; e < 4; e++) o[i][j][e] = 0.f;
    float l[4] = {0.f, 0.f, 0.f, 0.f};

    for (int ch = 0; ch < 16; ch++) {
        CP_WAIT0();             // chunk ch landed (its group is the only one left)
        __syncthreads();        // visible to all; prior AV readers of buf[(ch+1)&1] done

        if (ch < 15) stageKV(ch + 1);   // overlaps full chunk-ch compute

        const u32* Ks = Ksb + (ch & 1) * 64 * 72;
        const u32* Vs = Vsb + (ch & 1) * 64 * 72;

        // ---- S = Q @ K^T ----
        float s[2][2][4];
        #pragma unroll
        for (int i = 0; i < 2; i++)
            #pragma unroll
            for (int j = 0; j < 2; j++)
                #pragma unroll
                for (int e = 0; e < 4; e++) s[i][j][e] = 0.f;
        #pragma unroll
        for (int k8 = 0; k8 < 8; k8++) {
            u32 a[2][4], bb[2][2];
            #pragma unroll
            for (int i = 0; i < 2; i++) {
                const u32* p = Qs + (wm * 32 + 16 * i) * 68 + k8 * 8;
                a[i][0] = p[r4 * 68 + c4];
                a[i][1] = p[(r4 + 8) * 68 + c4];
                a[i][2] = p[r4 * 68 + c4 + 4];
                a[i][3] = p[(r4 + 8) * 68 + c4 + 4];
            }
            #pragma unroll
            for (int j = 0; j < 2; j++) {
                const u32* p = Ks + k8 * 8 * 72 + wn * 16 + 8 * j + r4;
                bb[j][0] = p[c4 * 72];
                bb[j][1] = p[(c4 + 4) * 72];
            }
            #pragma unroll
            for (int i = 0; i < 2; i++)
                #pragma unroll
                for (int j = 0; j < 2; j++)
                    mma_tf32(s[i][j], a[i], bb[j]);
        }

        // ---- exp -> P (tf32) + l of rounded values ----
        #pragma unroll
        for (int i = 0; i < 2; i++) {
            #pragma unroll
            for (int j = 0; j < 2; j++) {
                u32 t0 = to_tf32(__expf(s[i][j][0]));
                u32 t1 = to_tf32(__expf(s[i][j][1]));
                u32 t2 = to_tf32(__expf(s[i][j][2]));
                u32 t3 = to_tf32(__expf(s[i][j][3]));
                l[2 * i]     += __uint_as_float(t0) + __uint_as_float(t1);
                l[2 * i + 1] += __uint_as_float(t2) + __uint_as_float(t3);
                const int key = wn * 16 + 8 * j + 2 * c4;
                *(uint2*)&Ps[(wm * 32 + 16 * i + r4) * 68 + key]     = make_uint2(t0, t1);
                *(uint2*)&Ps[(wm * 32 + 16 * i + r4 + 8) * 68 + key] = make_uint2(t2, t3);
            }
        }
        __syncthreads();        // Ps visible

        // ---- O += P @ V ----
        #pragma unroll
        for (int k8 = 0; k8 < 8; k8++) {
            u32 a[2][4], bb[2][2];
            #pragma unroll
            for (int i = 0; i < 2; i++) {
                const u32* p = Ps + (wm * 32 + 16 * i) * 68 + k8 * 8;
                a[i][0] = p[r4 * 68 + c4];
                a[i][1] = p[(r4 + 8) * 68 + c4];
                a[i][2] = p[r4 * 68 + c4 + 4];
                a[i][3] = p[(r4 + 8) * 68 + c4 + 4];
            }
            #pragma unroll
            for (int j = 0; j < 2; j++) {
                const u32* p = Vs + k8 * 8 * 72 + wn * 16 + 8 * j + r4;
                bb[j][0] = p[c4 * 72];
                bb[j][1] = p[(c4 + 4) * 72];
            }
            #pragma unroll
            for (int i = 0; i < 2; i++)
                #pragma unroll
                for (int j = 0; j < 2; j++)
                    mma_tf32(o[i][j], a[i], bb[j]);
        }
    }

    // ---- l reduction ----
    #pragma unroll
    for (int e = 0; e < 4; e++) {
        float v = l[e];
        v += __shfl_xor_sync(0xffffffffu, v, 1);
        v += __shfl_xor_sync(0xffffffffu, v, 2);
        l[e] = v;
    }
    __syncthreads();
    if (c4 == 0) {
        atomicAdd(&Lsum[wm * 32 + r4],          l[0]);
        atomicAdd(&Lsum[wm * 32 + r4 + 8],      l[1]);
        atomicAdd(&Lsum[wm * 32 + 16 + r4],     l[2]);
        atomicAdd(&Lsum[wm * 32 + 16 + r4 + 8], l[3]);
    }
    __syncthreads();

    // ---- O / l -> [b][c][q], tf32-rounded ----
    #pragma unroll
    for (int i = 0; i < 2; i++) {
        #pragma unroll
        for (int half = 0; half < 2; half++) {
            const int ql = wm * 32 + 16 * i + r4 + 8 * half;
            const float inv = 1.f / Lsum[ql];
            const int q = q0 + ql;
            #pragma unroll
            for (int j = 0; j < 2; j++) {
                const int c = h * 64 + wn * 16 + 8 * j + 2 * c4;
                const size_t base = ((size_t)(b * DIM + c)) * HW + q;
                O[base]      = rndf(o[i][j][2 * half] * inv);
                O[base + HW] = rndf(o[i][j][2 * half + 1] * inv);
            }
        }
    }
}

// ---------------------------------------------------------------------------
// kernel_launch
// inputs: a, b, Wq, bq, Wk, bk, Wv, bv, Wp, bp, gnA_w, gnA_b, gnB_w, gnB_b
// ---------------------------------------------------------------------------
extern "C" void kernel_launch(void* const* d_in, const int* in_sizes, int n_in,
                              void* d_out, int out_size) {
    (void)in_sizes; (void)n_in; (void)out_size;
    const float* a    = (const float*)d_in[0];
    const float* bIn  = (const float*)d_in[1];
    const float* Wq   = (const float*)d_in[2];
    const float* bq   = (const float*)d_in[3];
    const float* Wk   = (const float*)d_in[4];
    const float* bk   = (const float*)d_in[5];
    const float* Wv   = (const float*)d_in[6];
    const float* bv   = (const float*)d_in[7];
    const float* Wp   = (const float*)d_in[8];
    const float* bp   = (const float*)d_in[9];
    const float* gnAw = (const float*)d_in[10];
    const float* gnAb = (const float*)d_in[11];
    const float* gnBw = (const float*)d_in[12];
    const float* gnBb = (const float*)d_in[13];
    float* out = (float*)d_out;

    float *an, *bn, *q, *k, *v, *hb, *wbuf;
    cudaGetSymbolAddress((void**)&an, g_an);
    cudaGetSymbolAddress((void**)&bn, g_bn);
    cudaGetSymbolAddress((void**)&q,  g_q);
    cudaGetSymbolAddress((void**)&k,  g_k);
    cudaGetSymbolAddress((void**)&v,  g_v);
    cudaGetSymbolAddress((void**)&hb, g_h);
    cudaGetSymbolAddress((void**)&wbuf, g_w);

    const int PROJ_SMEM = (2 * 128 * 36 + 2 * 32 * 136) * 4;       // 71680 B
    const int ATTN_SMEM = (2 * 64 * 68 + 4 * 64 * 72) * 4;         // 108544 B
    cudaFuncSetAttribute((const void*)qkv_kernel,   cudaFuncAttributeMaxDynamicSharedMemorySize, PROJ_SMEM);
    cudaFuncSetAttribute((const void*)final_kernel, cudaFuncAttributeMaxDynamicSharedMemorySize, PROJ_SMEM);
    cudaFuncSetAttribute((const void*)attn_kernel,  cudaFuncAttributeMaxDynamicSharedMemorySize, ATTN_SMEM);

    wconv_kernel<<<dim3(64, 4), 256>>>(Wq, Wk, Wv, Wp, wbuf);

    gn_kernel<<<dim3(32, BATCH, 2), 256>>>(a, bIn, gnAw, gnAb, gnBw, gnBb, an, bn);

    qkv_kernel<<<dim3(HW / 128, DIM / 128, 3 * BATCH), 256, PROJ_SMEM>>>(
        wbuf, an, bn, bq, bk, bv, q, k, v);

    attn_kernel<<<dim3(HW / 64, HEADS, BATCH), 256, ATTN_SMEM>>>(q, k, v, hb);

    final_kernel<<<dim3(HW / 128, DIM / 128, BATCH), 256, PROJ_SMEM>>>(
        wbuf + 3 * DIM * DIM, hb, bp, bIn, out);
}

// round 9
// speedup vs baseline: 1.0842x; 1.0842x over previous
#include <cuda_runtime.h>
#include <cstdint>

typedef unsigned int u32;

#define BATCH 16
#define DIM   256
#define HW    1024
#define HEADS 4

// Scratch (allocation-free rule: __device__ globals)
__device__ float g_an[BATCH * DIM * HW];   // [b][c][q]  (tf32-rounded)
__device__ float g_bn[BATCH * DIM * HW];   // [b][c][q]  (tf32-rounded)
__device__ float g_q [BATCH * DIM * HW];   // [bh][q][d] (x 1/16, tf32-rounded)
__device__ float g_k [BATCH * DIM * HW];   // [bh][d][q] (tf32-rounded)
__device__ float g_v [BATCH * DIM * HW];   // [bh][q][d] (tf32-rounded)
__device__ float g_h [BATCH * DIM * HW];   // [b][c][q]  (tf32-rounded)
__device__ float g_w [4 * DIM * DIM];      // rounded Wq,Wk,Wv,Wp

// ---------------------------------------------------------------------------
// Helpers
// ---------------------------------------------------------------------------
__device__ __forceinline__ void mma_tf32(float* d, const u32* a, const u32* b) {
    asm volatile(
        "mma.sync.aligned.m16n8k8.row.col.f32.tf32.tf32.f32 "
        "{%0,%1,%2,%3}, {%4,%5,%6,%7}, {%8,%9}, {%0,%1,%2,%3};"
        : "+f"(d[0]), "+f"(d[1]), "+f"(d[2]), "+f"(d[3])
        : "r"(a[0]), "r"(a[1]), "r"(a[2]), "r"(a[3]), "r"(b[0]), "r"(b[1]));
}
__device__ __forceinline__ u32 to_tf32(float f) {
    u32 r; asm("cvt.rna.tf32.f32 %0, %1;" : "=r"(r) : "f"(f)); return r;
}
__device__ __forceinline__ float rndf(float f) { return __uint_as_float(to_tf32(f)); }
__device__ __forceinline__ u32 smem_u32(const void* p) {
    u32 a;
    asm("{ .reg .u64 t; cvta.to.shared.u64 t, %1; cvt.u32.u64 %0, t; }" : "=r"(a) : "l"(p));
    return a;
}
__device__ __forceinline__ void cp16(u32 dst, const float* src) {
    asm volatile("cp.async.cg.shared.global [%0], [%1], 16;" :: "r"(dst), "l"(src));
}
#define CP_COMMIT() asm volatile("cp.async.commit_group;")
#define CP_WAIT0()  asm volatile("cp.async.wait_group 0;")
#define CP_WAIT1()  asm volatile("cp.async.wait_group 1;")

__inline__ __device__ float warpReduceSum(float v) {
    #pragma unroll
    for (int o = 16; o > 0; o >>= 1) v += __shfl_down_sync(0xffffffffu, v, o);
    return v;
}

// ---------------------------------------------------------------------------
// Weight pre-rounding: g_w[y] = rna_tf32(W_y)
// ---------------------------------------------------------------------------
__global__ __launch_bounds__(256)
void wconv_kernel(const float* __restrict__ w0, const float* __restrict__ w1,
                  const float* __restrict__ w2, const float* __restrict__ w3,
                  float* __restrict__ out) {
    const float* s = (blockIdx.y == 0) ? w0 : (blockIdx.y == 1) ? w1
                   : (blockIdx.y == 2) ? w2 : w3;
    int i = (blockIdx.x * 256 + threadIdx.x) * 4;
    float4 v = *(const float4*)(s + i);
    v.x = rndf(v.x); v.y = rndf(v.y); v.z = rndf(v.z); v.w = rndf(v.w);
    *(float4*)(out + (size_t)blockIdx.y * DIM * DIM + i) = v;
}

// ---------------------------------------------------------------------------
// GroupNorm (both tensors in one launch; z selects). [b][c][q] -> [b][c][q].
// ---------------------------------------------------------------------------
__global__ __launch_bounds__(256)
void gn_kernel(const float* __restrict__ xa, const float* __restrict__ xb,
               const float* __restrict__ gwA, const float* __restrict__ gbA,
               const float* __restrict__ gwB, const float* __restrict__ gbB,
               float* __restrict__ ya, float* __restrict__ yb) {
    const int g = blockIdx.x, b = blockIdx.y, t = threadIdx.x;
    const int which = blockIdx.z;
    const float* x = which ? xb : xa;
    const float* gamma = which ? gwB : gwA;
    const float* beta  = which ? gbB : gbA;
    float* y = which ? yb : ya;

    const int base = (b * DIM + g * 8) * HW;
    const float4* xp = (const float4*)(x + base);
    float4* yp = (float4*)(y + base);

    float4 r[8];
    float s = 0.f, s2 = 0.f;
    #pragma unroll
    for (int k = 0; k < 8; k++) {
        float4 v = xp[k * 256 + t];
        r[k] = v;
        s  += (v.x + v.y) + (v.z + v.w);
        s2 += (v.x * v.x + v.y * v.y) + (v.z * v.z + v.w * v.w);
    }
    s = warpReduceSum(s); s2 = warpReduceSum(s2);

    __shared__ float sh[2][8];
    int w = t >> 5, lane = t & 31;
    if (lane == 0) { sh[0][w] = s; sh[1][w] = s2; }
    __syncthreads();
    __shared__ float mu_s, inv_s;
    if (t == 0) {
        float S = 0.f, S2 = 0.f;
        #pragma unroll
        for (int i = 0; i < 8; i++) { S += sh[0][i]; S2 += sh[1][i]; }
        float mu = S * (1.0f / 8192.0f);
        float var = S2 * (1.0f / 8192.0f) - mu * mu;
        mu_s = mu; inv_s = rsqrtf(var + 1e-6f);
    }
    __syncthreads();
    const float mu = mu_s, inv = inv_s;

    #pragma unroll
    for (int k = 0; k < 8; k++) {
        int c = g * 8 + ((k * 256 + t) >> 8);
        float sc = inv * gamma[c];
        float shf = beta[c] - mu * sc;
        float4 v = r[k];
        v.x = rndf(v.x * sc + shf); v.y = rndf(v.y * sc + shf);
        v.z = rndf(v.z * sc + shf); v.w = rndf(v.w * sc + shf);
        yp[k * 256 + t] = v;
    }
}

// ---------------------------------------------------------------------------
// Shared GEMM core pieces (mma.sync tf32, cp.async staging).
// CTA tile M=128 x N=128, K=256 in 8 chunks of 32. 8 warps = 2(m) x 4(n).
// Smem: Ws[m][k] stride 36, Xs[k][n] stride 136 (conflict-free frags).
// ---------------------------------------------------------------------------
struct ProjCtx {
    u32 smb;
    int tid, wid, lane, r4, c4, wm, wn;
};

__device__ __forceinline__ void proj_stage(const ProjCtx& cx, int ch,
                                           const float* W, const float* Xb,
                                           int m0, int n0) {
    const int k0 = ch * 32;
    const u32 wd = cx.smb + (u32)((ch & 1) ? 128 * 36 * 4 : 0);
    const u32 xd = cx.smb + (u32)(2 * 128 * 36 * 4 + ((ch & 1) ? 32 * 136 * 4 : 0));
    #pragma unroll
    for (int r = 0; r < 4; r++) {
        int idx = r * 256 + cx.tid;
        int row = idx >> 3, col = (idx & 7) << 2;
        cp16(wd + (u32)(row * 36 + col) * 4, W + (size_t)(m0 + row) * DIM + k0 + col);
    }
    #pragma unroll
    for (int r = 0; r < 4; r++) {
        int idx = r * 256 + cx.tid;
        int row = idx >> 5, col = (idx & 31) << 2;
        cp16(xd + (u32)(row * 136 + col) * 4, Xb + (size_t)(k0 + row) * HW + n0 + col);
    }
    CP_COMMIT();
}

__device__ __forceinline__ void proj_mainloop(const ProjCtx& cx, const u32* dsm,
                                              const float* W, const float* Xb,
                                              int m0, int n0, float d[4][4][4]) {
    proj_stage(cx, 0, W, Xb, m0, n0);
    for (int ch = 0; ch < 8; ch++) {
        if (ch < 7) { proj_stage(cx, ch + 1, W, Xb, m0, n0); CP_WAIT1(); } else { CP_WAIT0(); }
        __syncthreads();
        const u32* Ws = dsm + ((ch & 1) ? 128 * 36 : 0);
        const u32* Xs = dsm + 2 * 128 * 36 + ((ch & 1) ? 32 * 136 : 0);
        #pragma unroll
        for (int k8 = 0; k8 < 4; k8++) {
            u32 a[4][4], bb[4][2];
            #pragma unroll
            for (int i = 0; i < 4; i++) {
                const u32* p = Ws + (cx.wm * 64 + 16 * i) * 36 + k8 * 8;
                a[i][0] = p[cx.r4 * 36 + cx.c4];
                a[i][1] = p[(cx.r4 + 8) * 36 + cx.c4];
                a[i][2] = p[cx.r4 * 36 + cx.c4 + 4];
                a[i][3] = p[(cx.r4 + 8) * 36 + cx.c4 + 4];
            }
            #pragma unroll
            for (int j = 0; j < 4; j++) {
                const u32* p = Xs + k8 * 8 * 136 + cx.wn * 32 + 8 * j + cx.r4;
                bb[j][0] = p[cx.c4 * 136];
                bb[j][1] = p[(cx.c4 + 4) * 136];
            }
            #pragma unroll
            for (int i = 0; i < 4; i++)
                #pragma unroll
                for (int j = 0; j < 4; j++)
                    mma_tf32(d[i][j], a[i], bb[j]);
        }
        __syncthreads();
    }
}

// ---------------------------------------------------------------------------
// QKV projection, one launch: z = proj*16 + b.  proj 0 = Q (x = bn, scale
// 1/16, out [bh][q][d]), 1 = K (out [bh][d][q]), 2 = V (out [bh][q][d]).
// ---------------------------------------------------------------------------
__global__ __launch_bounds__(256, 2)
void qkv_kernel(const float* __restrict__ wbuf,
                const float* __restrict__ an, const float* __restrict__ bn,
                const float* __restrict__ bq, const float* __restrict__ bk,
                const float* __restrict__ bv,
                float* __restrict__ Yq, float* __restrict__ Yk, float* __restrict__ Yv) {
    extern __shared__ u32 dsm[];
    ProjCtx cx;
    cx.smb = smem_u32(dsm);
    cx.tid = threadIdx.x; cx.wid = cx.tid >> 5; cx.lane = cx.tid & 31;
    cx.r4 = cx.lane >> 2; cx.c4 = cx.lane & 3;
    cx.wm = cx.wid >> 2; cx.wn = cx.wid & 3;

    const int pz = blockIdx.z >> 4;        // 0=Q 1=K 2=V
    const int b  = blockIdx.z & 15;
    const int n0 = blockIdx.x * 128, m0 = blockIdx.y * 128;
    const float* W  = wbuf + (size_t)pz * DIM * DIM;
    const float* Xb = ((pz == 0) ? bn : an) + (size_t)b * DIM * HW;
    const float* bias = (pz == 0) ? bq : (pz == 1) ? bk : bv;
    float* Y = (pz == 0) ? Yq : (pz == 1) ? Yk : Yv;

    float d[4][4][4];
    #pragma unroll
    for (int i = 0; i < 4; i++)
        #pragma unroll
        for (int j = 0; j < 4; j++)
            #pragma unroll
            for (int e = 0; e < 4; e++) d[i][j][e] = 0.f;

    proj_mainloop(cx, dsm, W, Xb, m0, n0, d);

    const float sc = (pz == 0) ? 0.0625f : 1.0f;
    #pragma unroll
    for (int i = 0; i < 4; i++) {
        #pragma unroll
        for (int half = 0; half < 2; half++) {
            const int m = m0 + cx.wm * 64 + 16 * i + cx.r4 + 8 * half;
            const float bvv = bias[m];
            const int hh = m >> 6, dd = m & 63;
            if (pz == 1) {
                float* Yh = Y + ((size_t)(b * HEADS + hh) << 16) + (size_t)dd * HW;
                #pragma unroll
                for (int j = 0; j < 4; j++) {
                    const int n = n0 + cx.wn * 32 + 8 * j + 2 * cx.c4;
                    float2 v = make_float2(rndf(d[i][j][2 * half] + bvv),
                                           rndf(d[i][j][2 * half + 1] + bvv));
                    *(float2*)(Yh + n) = v;
                }
            } else {
                float* Yh = Y + ((size_t)(b * HEADS + hh) << 16) + dd;
                #pragma unroll
                for (int j = 0; j < 4; j++) {
                    const int n = n0 + cx.wn * 32 + 8 * j + 2 * cx.c4;
                    Yh[(size_t)n * 64]       = rndf((d[i][j][2 * half] + bvv) * sc);
                    Yh[(size_t)(n + 1) * 64] = rndf((d[i][j][2 * half + 1] + bvv) * sc);
                }
            }
        }
    }
}

// ---------------------------------------------------------------------------
// Final projection: out[b][m][q] = (Wp @ h + bias + skip) / sqrt(2)
// ---------------------------------------------------------------------------
__global__ __launch_bounds__(256, 2)
void final_kernel(const float* __restrict__ W, const float* __restrict__ X,
                  const float* __restrict__ bias, const float* __restrict__ skip,
                  float* __restrict__ Y) {
    extern __shared__ u32 dsm[];
    ProjCtx cx;
    cx.smb = smem_u32(dsm);
    cx.tid = threadIdx.x; cx.wid = cx.tid >> 5; cx.lane = cx.tid & 31;
    cx.r4 = cx.lane >> 2; cx.c4 = cx.lane & 3;
    cx.wm = cx.wid >> 2; cx.wn = cx.wid & 3;

    const int n0 = blockIdx.x * 128, m0 = blockIdx.y * 128, b = blockIdx.z;
    const float* Xb = X + (size_t)b * DIM * HW;

    float d[4][4][4];
    #pragma unroll
    for (int i = 0; i < 4; i++)
        #pragma unroll
        for (int j = 0; j < 4; j++)
            #pragma unroll
            for (int e = 0; e < 4; e++) d[i][j][e] = 0.f;

    proj_mainloop(cx, dsm, W, Xb, m0, n0, d);

    const float r2 = 0.7071067811865476f;
    #pragma unroll
    for (int i = 0; i < 4; i++) {
        #pragma unroll
        for (int half = 0; half < 2; half++) {
            const int m = m0 + cx.wm * 64 + 16 * i + cx.r4 + 8 * half;
            const float bvv = bias[m];
            const size_t rowb = ((size_t)b * DIM + m) * HW;
            #pragma unroll
            for (int j = 0; j < 4; j++) {
                const int n = n0 + cx.wn * 32 + 8 * j + 2 * cx.c4;
                float2 sk = *(const float2*)(skip + rowb + n);
                float2 v = make_float2((d[i][j][2 * half] + bvv + sk.x) * r2,
                                       (d[i][j][2 * half + 1] + bvv + sk.y) * r2);
                *(float2*)(Y + rowb + n) = v;
            }
        }
    }
}

// ---------------------------------------------------------------------------
// Attention (R7 structure — measured best). CTA = (128 q, head, batch),
// 256 threads = 8 warps (4 m x 2 n). 16 key-chunks of 64:
//   S = Q @ K^T -> exp -> P (tf32, smem) -> O += P @ V.
// Single-buffered K/V, loads sequenced so V latency hides under S+exp and
// K(ch+1) hides under AV. Smem: Qs[128][68], Ks[64][72] ([d][key]),
// Vs[64][72] ([key][d]), Ps[128][68] = 106496 B -> occupancy 2.
// ---------------------------------------------------------------------------
__global__ __launch_bounds__(256, 2)
void attn_kernel(const float* __restrict__ Qg, const float* __restrict__ Kg,
                 const float* __restrict__ Vg, float* __restrict__ O) {
    extern __shared__ u32 dsm[];
    u32* Qs = dsm;                       // 128 x 68
    u32* Ks = Qs + 128 * 68;             // 64 x 72
    u32* Vs = Ks + 64 * 72;              // 64 x 72
    u32* Ps = Vs + 64 * 72;              // 128 x 68
    __shared__ float Lsum[128];
    const u32 smb = smem_u32(dsm);
    const u32 QsA = smb;
    const u32 KsA = smb + 128 * 68 * 4;
    const u32 VsA = KsA + 64 * 72 * 4;

    const int tid = threadIdx.x;
    const int wid = tid >> 5, lane = tid & 31;
    const int r4 = lane >> 2, c4 = lane & 3;
    const int wm = wid >> 1, wn = wid & 1;
    const int q0 = blockIdx.x * 128;
    const int h = blockIdx.y, b = blockIdx.z;
    const int bh = b * HEADS + h;
    const float* Qb = Qg + ((size_t)bh << 16);   // [q][d]
    const float* Kb = Kg + ((size_t)bh << 16);   // [d][key]
    const float* Vb = Vg + ((size_t)bh << 16);   // [key][d]

    // stage Q (once) + K0 + V0 as one cp.async group
    #pragma unroll
    for (int r = 0; r < 8; r++) {
        int idx = r * 256 + tid;
        int row = idx >> 4, col = (idx & 15) << 2;
        cp16(QsA + (u32)(row * 68 + col) * 4, Qb + (size_t)(q0 + row) * 64 + col);
    }
    #pragma unroll
    for (int r = 0; r < 4; r++) {
        int idx = r * 256 + tid;
        int row = idx >> 4, col = (idx & 15) << 2;
        cp16(KsA + (u32)(row * 72 + col) * 4, Kb + (size_t)row * HW + col);
        cp16(VsA + (u32)(row * 72 + col) * 4, Vb + (size_t)row * 64 + col);
    }
    CP_COMMIT();
    if (tid < 128) Lsum[tid] = 0.f;

    float o[2][4][4];
    #pragma unroll
    for (int i = 0; i < 2; i++)
        #pragma unroll
        for (int j = 0; j < 4; j++)
            #pragma unroll
            for (int e = 0; e < 4; e++) o[i][j][e] = 0.f;
    float l[4] = {0.f, 0.f, 0.f, 0.f};

    for (int ch = 0; ch < 16; ch++) {
        if (ch == 0) { CP_WAIT0(); } else { CP_WAIT1(); }   // K(ch) ready; V(ch) may lag
        __syncthreads();

        // ---- S = Q @ K^T ----
        float s[2][4][4];
        #pragma unroll
        for (int i = 0; i < 2; i++)
            #pragma unroll
            for (int j = 0; j < 4; j++)
                #pragma unroll
                for (int e = 0; e < 4; e++) s[i][j][e] = 0.f;
        #pragma unroll
        for (int k8 = 0; k8 < 8; k8++) {
            u32 a[2][4], bb[4][2];
            #pragma unroll
            for (int i = 0; i < 2; i++) {
                const u32* p = Qs + (wm * 32 + 16 * i) * 68 + k8 * 8;
                a[i][0] = p[r4 * 68 + c4];
                a[i][1] = p[(r4 + 8) * 68 + c4];
                a[i][2] = p[r4 * 68 + c4 + 4];
                a[i][3] = p[(r4 + 8) * 68 + c4 + 4];
            }
            #pragma unroll
            for (int j = 0; j < 4; j++) {
                const u32* p = Ks + k8 * 8 * 72 + wn * 32 + 8 * j + r4;
                bb[j][0] = p[c4 * 72];
                bb[j][1] = p[(c4 + 4) * 72];
            }
            #pragma unroll
            for (int i = 0; i < 2; i++)
                #pragma unroll
                for (int j = 0; j < 4; j++)
                    mma_tf32(s[i][j], a[i], bb[j]);
        }

        // ---- exp -> P (tf32) + l of rounded values ----
        #pragma unroll
        for (int i = 0; i < 2; i++) {
            #pragma unroll
            for (int j = 0; j < 4; j++) {
                u32 t0 = to_tf32(__expf(s[i][j][0]));
                u32 t1 = to_tf32(__expf(s[i][j][1]));
                u32 t2 = to_tf32(__expf(s[i][j][2]));
                u32 t3 = to_tf32(__expf(s[i][j][3]));
                l[2 * i]     += __uint_as_float(t0) + __uint_as_float(t1);
                l[2 * i + 1] += __uint_as_float(t2) + __uint_as_float(t3);
                const int key = wn * 32 + 8 * j + 2 * c4;
                *(uint2*)&Ps[(wm * 32 + 16 * i + r4) * 68 + key]     = make_uint2(t0, t1);
                *(uint2*)&Ps[(wm * 32 + 16 * i + r4 + 8) * 68 + key] = make_uint2(t2, t3);
            }
        }
        __syncthreads();                    // Ks free; Ps visible

        if (ch < 15) {                      // K(ch+1) overlaps AV below
            const int kb = (ch + 1) * 64;
            #pragma unroll
            for (int r = 0; r < 4; r++) {
                int idx = r * 256 + tid;
                int row = idx >> 4, col = (idx & 15) << 2;
                cp16(KsA + (u32)(row * 72 + col) * 4, Kb + (size_t)row * HW + kb + col);
            }
            CP_COMMIT();
            CP_WAIT1();                     // V(ch) done; K(ch+1) pending
        } else {
            CP_WAIT0();                     // V(15) done
        }
        __syncthreads();                    // V(ch) visible to all

        // ---- O += P @ V ----
        #pragma unroll
        for (int k8 = 0; k8 < 8; k8++) {
            u32 a[2][4], bb[4][2];
            #pragma unroll
            for (int i = 0; i < 2; i++) {
                const u32* p = Ps + (wm * 32 + 16 * i) * 68 + k8 * 8;
                a[i][0] = p[r4 * 68 + c4];
                a[i][1] = p[(r4 + 8) * 68 + c4];
                a[i][2] = p[r4 * 68 + c4 + 4];
                a[i][3] = p[(r4 + 8) * 68 + c4 + 4];
            }
            #pragma unroll
            for (int j = 0; j < 4; j++) {
                const u32* p = Vs + k8 * 8 * 72 + wn * 32 + 8 * j + r4;
                bb[j][0] = p[c4 * 72];
                bb[j][1] = p[(c4 + 4) * 72];
            }
            #pragma unroll
            for (int i = 0; i < 2; i++)
                #pragma unroll
                for (int j = 0; j < 4; j++)
                    mma_tf32(o[i][j], a[i], bb[j]);
        }
        __syncthreads();                    // Vs free

        if (ch < 15) {                      // V(ch+1)
            const int kb = (ch + 1) * 64;
            #pragma unroll
            for (int r = 0; r < 4; r++) {
                int idx = r * 256 + tid;
                int row = idx >> 4, col = (idx & 15) << 2;
                cp16(VsA + (u32)(row * 72 + col) * 4, Vb + (size_t)(kb + row) * 64 + col);
            }
            CP_COMMIT();
        }
    }

    // ---- l reduction (over c4 lanes, then across wn via smem atomics) ----
    #pragma unroll
    for (int e = 0; e < 4; e++) {
        float v = l[e];
        v += __shfl_xor_sync(0xffffffffu, v, 1);
        v += __shfl_xor_sync(0xffffffffu, v, 2);
        l[e] = v;
    }
    if (c4 == 0) {
        atomicAdd(&Lsum[wm * 32 + r4],          l[0]);
        atomicAdd(&Lsum[wm * 32 + r4 + 8],      l[1]);
        atomicAdd(&Lsum[wm * 32 + 16 + r4],     l[2]);
        atomicAdd(&Lsum[wm * 32 + 16 + r4 + 8], l[3]);
    }
    __syncthreads();

    // ---- O / l -> [b][c][q], tf32-rounded (feeds final projection) ----
    #pragma unroll
    for (int i = 0; i < 2; i++) {
        #pragma unroll
        for (int half = 0; half < 2; half++) {
            const int ql = wm * 32 + 16 * i + r4 + 8 * half;
            const float inv = 1.f / Lsum[ql];
            const int q = q0 + ql;
            #pragma unroll
            for (int j = 0; j < 4; j++) {
                const int c = h * 64 + wn * 32 + 8 * j + 2 * c4;
                const size_t base = ((size_t)(b * DIM + c)) * HW + q;
                O[base]      = rndf(o[i][j][2 * half] * inv);
                O[base + HW] = rndf(o[i][j][2 * half + 1] * inv);
            }
        }
    }
}

// ---------------------------------------------------------------------------
// kernel_launch
// inputs: a, b, Wq, bq, Wk, bk, Wv, bv, Wp, bp, gnA_w, gnA_b, gnB_w, gnB_b
// ---------------------------------------------------------------------------
extern "C" void kernel_launch(void* const* d_in, const int* in_sizes, int n_in,
                              void* d_out, int out_size) {
    (void)in_sizes; (void)n_in; (void)out_size;
    const float* a    = (const float*)d_in[0];
    const float* bIn  = (const float*)d_in[1];
    const float* Wq   = (const float*)d_in[2];
    const float* bq   = (const float*)d_in[3];
    const float* Wk   = (const float*)d_in[4];
    const float* bk   = (const float*)d_in[5];
    const float* Wv   = (const float*)d_in[6];
    const float* bv   = (const float*)d_in[7];
    const float* Wp   = (const float*)d_in[8];
    const float* bp   = (const float*)d_in[9];
    const float* gnAw = (const float*)d_in[10];
    const float* gnAb = (const float*)d_in[11];
    const float* gnBw = (const float*)d_in[12];
    const float* gnBb = (const float*)d_in[13];
    float* out = (float*)d_out;

    float *an, *bn, *q, *k, *v, *hb, *wbuf;
    cudaGetSymbolAddress((void**)&an, g_an);
    cudaGetSymbolAddress((void**)&bn, g_bn);
    cudaGetSymbolAddress((void**)&q,  g_q);
    cudaGetSymbolAddress((void**)&k,  g_k);
    cudaGetSymbolAddress((void**)&v,  g_v);
    cudaGetSymbolAddress((void**)&hb, g_h);
    cudaGetSymbolAddress((void**)&wbuf, g_w);

    const int PROJ_SMEM = (2 * 128 * 36 + 2 * 32 * 136) * 4;       // 71680 B
    const int ATTN_SMEM = (2 * 128 * 68 + 2 * 64 * 72) * 4;        // 106496 B
    cudaFuncSetAttribute((const void*)qkv_kernel,   cudaFuncAttributeMaxDynamicSharedMemorySize, PROJ_SMEM);
    cudaFuncSetAttribute((const void*)final_kernel, cudaFuncAttributeMaxDynamicSharedMemorySize, PROJ_SMEM);
    cudaFuncSetAttribute((const void*)attn_kernel,  cudaFuncAttributeMaxDynamicSharedMemorySize, ATTN_SMEM);

    wconv_kernel<<<dim3(64, 4), 256>>>(Wq, Wk, Wv, Wp, wbuf);

    gn_kernel<<<dim3(32, BATCH, 2), 256>>>(a, bIn, gnAw, gnAb, gnBw, gnBb, an, bn);

    qkv_kernel<<<dim3(HW / 128, DIM / 128, 3 * BATCH), 256, PROJ_SMEM>>>(
        wbuf, an, bn, bq, bk, bv, q, k, v);

    attn_kernel<<<dim3(HW / 128, HEADS, BATCH), 256, ATTN_SMEM>>>(q, k, v, hb);

    final_kernel<<<dim3(HW / 128, DIM / 128, BATCH), 256, PROJ_SMEM>>>(
        wbuf + 3 * DIM * DIM, hb, bp, bIn, out);
}

// round 10
// speedup vs baseline: 1.0977x; 1.0125x over previous
#include <cuda_runtime.h>
#include <cstdint>

typedef unsigned int u32;

#define BATCH 16
#define DIM   256
#define HW    1024
#define HEADS 4

// Scratch (allocation-free rule: __device__ globals)
__device__ float g_an[BATCH * DIM * HW];   // [b][c][q]  (tf32-rounded)
__device__ float g_bn[BATCH * DIM * HW];   // [b][c][q]  (tf32-rounded)
__device__ float g_q [BATCH * DIM * HW];   // [bh][q][d_perm] (x 1/16, rounded)
__device__ float g_k [BATCH * DIM * HW];   // [bh][q][d_perm] (rounded)
__device__ float g_v [BATCH * DIM * HW];   // [bh][d][key_perm] (rounded)
__device__ float g_h [BATCH * DIM * HW];   // [b][c][q]  (rounded)
__device__ float g_w [4 * DIM * DIM];      // rounded + k-permuted Wq,Wk,Wv,Wp

// ---------------------------------------------------------------------------
// Helpers
// ---------------------------------------------------------------------------
__device__ __forceinline__ void mma_tf32(float* d, const u32* a, const u32* b) {
    asm volatile(
        "mma.sync.aligned.m16n8k8.row.col.f32.tf32.tf32.f32 "
        "{%0,%1,%2,%3}, {%4,%5,%6,%7}, {%8,%9}, {%0,%1,%2,%3};"
        : "+f"(d[0]), "+f"(d[1]), "+f"(d[2]), "+f"(d[3])
        : "r"(a[0]), "r"(a[1]), "r"(a[2]), "r"(a[3]), "r"(b[0]), "r"(b[1]));
}
__device__ __forceinline__ u32 to_tf32(float f) {
    u32 r; asm("cvt.rna.tf32.f32 %0, %1;" : "=r"(r) : "f"(f)); return r;
}
__device__ __forceinline__ float rndf(float f) { return __uint_as_float(to_tf32(f)); }
__device__ __forceinline__ u32 smem_u32(const void* p) {
    u32 a;
    asm("{ .reg .u64 t; cvta.to.shared.u64 t, %1; cvt.u32.u64 %0, t; }" : "=r"(a) : "l"(p));
    return a;
}
__device__ __forceinline__ void cp16(u32 dst, const float* src) {
    asm volatile("cp.async.cg.shared.global [%0], [%1], 16;" :: "r"(dst), "l"(src));
}
#define CP_COMMIT() asm volatile("cp.async.commit_group;")
#define CP_WAIT0()  asm volatile("cp.async.wait_group 0;")
#define CP_WAIT1()  asm volatile("cp.async.wait_group 1;")

// within-8-block pair permutation: x<4 -> 2x ; x>=4 -> 2x-7
__device__ __forceinline__ int perm8(int k) {
    int x = k & 7;
    return (k & ~7) + ((x < 4) ? (2 * x) : (2 * x - 7));
}

__inline__ __device__ float warpReduceSum(float v) {
    #pragma unroll
    for (int o = 16; o > 0; o >>= 1) v += __shfl_down_sync(0xffffffffu, v, o);
    return v;
}

// ---------------------------------------------------------------------------
// Weight pre-round + k-permute: g_w[y][m][perm(k)] = rna_tf32(W_y[m][k])
// ---------------------------------------------------------------------------
__global__ __launch_bounds__(256)
void wconv_kernel(const float* __restrict__ w0, const float* __restrict__ w1,
                  const float* __restrict__ w2, const float* __restrict__ w3,
                  float* __restrict__ out) {
    const float* s = (blockIdx.y == 0) ? w0 : (blockIdx.y == 1) ? w1
                   : (blockIdx.y == 2) ? w2 : w3;
    int i = (blockIdx.x * 256 + threadIdx.x) * 4;   // m*256 + k0 (k0 % 4 == 0)
    float4 v = *(const float4*)(s + i);
    float* ob = out + (size_t)blockIdx.y * DIM * DIM + (i & ~7) + ((i & 4) ? 1 : 0);
    ob[0] = rndf(v.x); ob[2] = rndf(v.y); ob[4] = rndf(v.z); ob[6] = rndf(v.w);
}

// ---------------------------------------------------------------------------
// GroupNorm (both tensors in one launch; z selects). [b][c][q] -> [b][c][q].
// ---------------------------------------------------------------------------
__global__ __launch_bounds__(256)
void gn_kernel(const float* __restrict__ xa, const float* __restrict__ xb,
               const float* __restrict__ gwA, const float* __restrict__ gbA,
               const float* __restrict__ gwB, const float* __restrict__ gbB,
               float* __restrict__ ya, float* __restrict__ yb) {
    const int g = blockIdx.x, b = blockIdx.y, t = threadIdx.x;
    const int which = blockIdx.z;
    const float* x = which ? xb : xa;
    const float* gamma = which ? gwB : gwA;
    const float* beta  = which ? gbB : gbA;
    float* y = which ? yb : ya;

    const int base = (b * DIM + g * 8) * HW;
    const float4* xp = (const float4*)(x + base);
    float4* yp = (float4*)(y + base);

    float4 r[8];
    float s = 0.f, s2 = 0.f;
    #pragma unroll
    for (int k = 0; k < 8; k++) {
        float4 v = xp[k * 256 + t];
        r[k] = v;
        s  += (v.x + v.y) + (v.z + v.w);
        s2 += (v.x * v.x + v.y * v.y) + (v.z * v.z + v.w * v.w);
    }
    s = warpReduceSum(s); s2 = warpReduceSum(s2);

    __shared__ float sh[2][8];
    int w = t >> 5, lane = t & 31;
    if (lane == 0) { sh[0][w] = s; sh[1][w] = s2; }
    __syncthreads();
    __shared__ float mu_s, inv_s;
    if (t == 0) {
        float S = 0.f, S2 = 0.f;
        #pragma unroll
        for (int i = 0; i < 8; i++) { S += sh[0][i]; S2 += sh[1][i]; }
        float mu = S * (1.0f / 8192.0f);
        float var = S2 * (1.0f / 8192.0f) - mu * mu;
        mu_s = mu; inv_s = rsqrtf(var + 1e-6f);
    }
    __syncthreads();
    const float mu = mu_s, inv = inv_s;

    #pragma unroll
    for (int k = 0; k < 8; k++) {
        int c = g * 8 + ((k * 256 + t) >> 8);
        float sc = inv * gamma[c];
        float shf = beta[c] - mu * sc;
        float4 v = r[k];
        v.x = rndf(v.x * sc + shf); v.y = rndf(v.y * sc + shf);
        v.z = rndf(v.z * sc + shf); v.w = rndf(v.w * sc + shf);
        yp[k * 256 + t] = v;
    }
}

// ---------------------------------------------------------------------------
// Shared GEMM core (mma.sync tf32, cp.async). CTA M=128 x N=128, K=256 in 8
// chunks of 32. 8 warps = 2(m) x 4(n). W is k-permuted -> A-frags are paired
// 64-bit LDS. Smem: Ws[m][k_perm] stride 40, Xs[k][n] stride 136.
// ---------------------------------------------------------------------------
struct ProjCtx {
    u32 smb;
    int tid, wid, lane, r4, c4, wm, wn;
};

__device__ __forceinline__ void proj_stage(const ProjCtx& cx, int ch,
                                           const float* W, const float* Xb,
                                           int m0, int n0) {
    const int k0 = ch * 32;
    const u32 wd = cx.smb + (u32)((ch & 1) ? 128 * 40 * 4 : 0);
    const u32 xd = cx.smb + (u32)(2 * 128 * 40 * 4 + ((ch & 1) ? 32 * 136 * 4 : 0));
    #pragma unroll
    for (int r = 0; r < 4; r++) {
        int idx = r * 256 + cx.tid;
        int row = idx >> 3, col = (idx & 7) << 2;
        cp16(wd + (u32)(row * 40 + col) * 4, W + (size_t)(m0 + row) * DIM + k0 + col);
    }
    #pragma unroll
    for (int r = 0; r < 4; r++) {
        int idx = r * 256 + cx.tid;
        int row = idx >> 5, col = (idx & 31) << 2;
        cp16(xd + (u32)(row * 136 + col) * 4, Xb + (size_t)(k0 + row) * HW + n0 + col);
    }
    CP_COMMIT();
}

__device__ __forceinline__ void proj_mainloop(const ProjCtx& cx, const u32* dsm,
                                              const float* W, const float* Xb,
                                              int m0, int n0, float d[4][4][4]) {
    proj_stage(cx, 0, W, Xb, m0, n0);
    for (int ch = 0; ch < 8; ch++) {
        if (ch < 7) { proj_stage(cx, ch + 1, W, Xb, m0, n0); CP_WAIT1(); } else { CP_WAIT0(); }
        __syncthreads();
        const u32* Ws = dsm + ((ch & 1) ? 128 * 40 : 0);
        const u32* Xs = dsm + 2 * 128 * 40 + ((ch & 1) ? 32 * 136 : 0);
        #pragma unroll
        for (int k8 = 0; k8 < 4; k8++) {
            u32 a[4][4], bb[4][2];
            #pragma unroll
            for (int i = 0; i < 4; i++) {
                const u32* p = Ws + (cx.wm * 64 + 16 * i) * 40 + k8 * 8 + 2 * cx.c4;
                uint2 lo = *(const uint2*)&p[cx.r4 * 40];
                uint2 hi = *(const uint2*)&p[(cx.r4 + 8) * 40];
                a[i][0] = lo.x; a[i][2] = lo.y;
                a[i][1] = hi.x; a[i][3] = hi.y;
            }
            #pragma unroll
            for (int j = 0; j < 4; j++) {
                const u32* p = Xs + k8 * 8 * 136 + cx.wn * 32 + 8 * j + cx.r4;
                bb[j][0] = p[cx.c4 * 136];
                bb[j][1] = p[(cx.c4 + 4) * 136];
            }
            #pragma unroll
            for (int i = 0; i < 4; i++)
                #pragma unroll
                for (int j = 0; j < 4; j++)
                    mma_tf32(d[i][j], a[i], bb[j]);
        }
        __syncthreads();
    }
}

// ---------------------------------------------------------------------------
// QKV projection, one launch: z = proj*16 + b.
// proj 0 = Q -> [bh][q][d_perm] x(1/16); 1 = K -> [bh][q][d_perm];
// proj 2 = V -> [bh][d][key_perm].
// ---------------------------------------------------------------------------
__global__ __launch_bounds__(256, 2)
void qkv_kernel(const float* __restrict__ wbuf,
                const float* __restrict__ an, const float* __restrict__ bn,
                const float* __restrict__ bq, const float* __restrict__ bk,
                const float* __restrict__ bv,
                float* __restrict__ Yq, float* __restrict__ Yk, float* __restrict__ Yv) {
    extern __shared__ u32 dsm[];
    ProjCtx cx;
    cx.smb = smem_u32(dsm);
    cx.tid = threadIdx.x; cx.wid = cx.tid >> 5; cx.lane = cx.tid & 31;
    cx.r4 = cx.lane >> 2; cx.c4 = cx.lane & 3;
    cx.wm = cx.wid >> 2; cx.wn = cx.wid & 3;

    const int pz = blockIdx.z >> 4;        // 0=Q 1=K 2=V
    const int b  = blockIdx.z & 15;
    const int n0 = blockIdx.x * 128, m0 = blockIdx.y * 128;
    const float* W  = wbuf + (size_t)pz * DIM * DIM;
    const float* Xb = ((pz == 0) ? bn : an) + (size_t)b * DIM * HW;
    const float* bias = (pz == 0) ? bq : (pz == 1) ? bk : bv;
    float* Y = (pz == 0) ? Yq : (pz == 1) ? Yk : Yv;

    float d[4][4][4];
    #pragma unroll
    for (int i = 0; i < 4; i++)
        #pragma unroll
        for (int j = 0; j < 4; j++)
            #pragma unroll
            for (int e = 0; e < 4; e++) d[i][j][e] = 0.f;

    proj_mainloop(cx, dsm, W, Xb, m0, n0, d);

    const float sc = (pz == 0) ? 0.0625f : 1.0f;
    const int pos = (cx.c4 < 2) ? 4 * cx.c4 : 4 * cx.c4 - 7;   // perm of key 2*c4
    #pragma unroll
    for (int i = 0; i < 4; i++) {
        #pragma unroll
        for (int half = 0; half < 2; half++) {
            const int m = m0 + cx.wm * 64 + 16 * i + cx.r4 + 8 * half;
            const float bvv = bias[m];
            const int hh = m >> 6, dd = m & 63;
            if (pz == 2) {
                // V: [bh][d][key_perm]
                float* Yh = Y + ((size_t)(b * HEADS + hh) << 16) + (size_t)dd * HW;
                #pragma unroll
                for (int j = 0; j < 4; j++) {
                    const int nblk = n0 + cx.wn * 32 + 8 * j;
                    Yh[nblk + pos]     = rndf(d[i][j][2 * half] + bvv);
                    Yh[nblk + pos + 2] = rndf(d[i][j][2 * half + 1] + bvv);
                }
            } else {
                // Q/K: [bh][q][d_perm]
                const int ddp = perm8(dd);
                float* Yh = Y + ((size_t)(b * HEADS + hh) << 16) + ddp;
                #pragma unroll
                for (int j = 0; j < 4; j++) {
                    const int n = n0 + cx.wn * 32 + 8 * j + 2 * cx.c4;
                    Yh[(size_t)n * 64]       = rndf((d[i][j][2 * half] + bvv) * sc);
                    Yh[(size_t)(n + 1) * 64] = rndf((d[i][j][2 * half + 1] + bvv) * sc);
                }
            }
        }
    }
}

// ---------------------------------------------------------------------------
// Final projection: out[b][m][q] = (Wp @ h + bias + skip) / sqrt(2)
// ---------------------------------------------------------------------------
__global__ __launch_bounds__(256, 2)
void final_kernel(const float* __restrict__ W, const float* __restrict__ X,
                  const float* __restrict__ bias, const float* __restrict__ skip,
                  float* __restrict__ Y) {
    extern __shared__ u32 dsm[];
    ProjCtx cx;
    cx.smb = smem_u32(dsm);
    cx.tid = threadIdx.x; cx.wid = cx.tid >> 5; cx.lane = cx.tid & 31;
    cx.r4 = cx.lane >> 2; cx.c4 = cx.lane & 3;
    cx.wm = cx.wid >> 2; cx.wn = cx.wid & 3;

    const int n0 = blockIdx.x * 128, m0 = blockIdx.y * 128, b = blockIdx.z;
    const float* Xb = X + (size_t)b * DIM * HW;

    float d[4][4][4];
    #pragma unroll
    for (int i = 0; i < 4; i++)
        #pragma unroll
        for (int j = 0; j < 4; j++)
            #pragma unroll
            for (int e = 0; e < 4; e++) d[i][j][e] = 0.f;

    proj_mainloop(cx, dsm, W, Xb, m0, n0, d);

    const float r2 = 0.7071067811865476f;
    #pragma unroll
    for (int i = 0; i < 4; i++) {
        #pragma unroll
        for (int half = 0; half < 2; half++) {
            const int m = m0 + cx.wm * 64 + 16 * i + cx.r4 + 8 * half;
            const float bvv = bias[m];
            const size_t rowb = ((size_t)b * DIM + m) * HW;
            #pragma unroll
            for (int j = 0; j < 4; j++) {
                const int n = n0 + cx.wn * 32 + 8 * j + 2 * cx.c4;
                float2 sk = *(const float2*)(skip + rowb + n);
                float2 v = make_float2((d[i][j][2 * half] + bvv + sk.x) * r2,
                                       (d[i][j][2 * half + 1] + bvv + sk.y) * r2);
                *(float2*)(Y + rowb + n) = v;
            }
        }
    }
}

// ---------------------------------------------------------------------------
// Attention. CTA = (128 q, head, batch), 256 threads = 8 warps (4m x 2n).
// All k-dims pair-permuted -> every fragment gather is one 64-bit LDS.
// Smem: Qs[128][72] ([q][d_perm]), Ps[128][72] ([q][key_perm]),
//       Ks[64][72] ([key][d_perm]), Vs[64][72] ([d][key_perm]) = 110592 B.
// Load sequencing as R7: V latency hides under S+exp, K(ch+1) under AV.
// ---------------------------------------------------------------------------
__global__ __launch_bounds__(256, 2)
void attn_kernel(const float* __restrict__ Qg, const float* __restrict__ Kg,
                 const float* __restrict__ Vg, float* __restrict__ O) {
    extern __shared__ u32 dsm[];
    u32* Qs = dsm;                       // 128 x 72
    u32* Ps = Qs + 128 * 72;             // 128 x 72
    u32* Ks = Ps + 128 * 72;             // 64 x 72
    u32* Vs = Ks + 64 * 72;              // 64 x 72
    __shared__ float Lsum[128];
    const u32 smb = smem_u32(dsm);
    const u32 QsA = smb;
    const u32 KsA = smb + (2 * 128 * 72) * 4;
    const u32 VsA = KsA + 64 * 72 * 4;

    const int tid = threadIdx.x;
    const int wid = tid >> 5, lane = tid & 31;
    const int r4 = lane >> 2, c4 = lane & 3;
    const int wm = wid >> 1, wn = wid & 1;
    const int q0 = blockIdx.x * 128;
    const int h = blockIdx.y, b = blockIdx.z;
    const int bh = b * HEADS + h;
    const float* Qb = Qg + ((size_t)bh << 16);   // [q][d_perm]
    const float* Kb = Kg + ((size_t)bh << 16);   // [key][d_perm]
    const float* Vb = Vg + ((size_t)bh << 16);   // [d][key_perm]

    // stage Q (once) + K0 + V0 as one cp.async group
    #pragma unroll
    for (int r = 0; r < 8; r++) {
        int idx = r * 256 + tid;
        int row = idx >> 4, col = (idx & 15) << 2;
        cp16(QsA + (u32)(row * 72 + col) * 4, Qb + (size_t)(q0 + row) * 64 + col);
    }
    #pragma unroll
    for (int r = 0; r < 4; r++) {
        int idx = r * 256 + tid;
        int row = idx >> 4, col = (idx & 15) << 2;
        cp16(KsA + (u32)(row * 72 + col) * 4, Kb + (size_t)row * 64 + col);
        cp16(VsA + (u32)(row * 72 + col) * 4, Vb + (size_t)row * HW + col);
    }
    CP_COMMIT();
    if (tid < 128) Lsum[tid] = 0.f;

    float o[2][4][4];
    #pragma unroll
    for (int i = 0; i < 2; i++)
        #pragma unroll
        for (int j = 0; j < 4; j++)
            #pragma unroll
            for (int e = 0; e < 4; e++) o[i][j][e] = 0.f;
    float l[4] = {0.f, 0.f, 0.f, 0.f};

    const int pos = (c4 < 2) ? 4 * c4 : 4 * c4 - 7;   // perm of key 2*c4

    for (int ch = 0; ch < 16; ch++) {
        if (ch == 0) { CP_WAIT0(); } else { CP_WAIT1(); }   // K(ch) ready; V(ch) may lag
        __syncthreads();

        // ---- S = Q @ K^T (paired frags) ----
        float s[2][4][4];
        #pragma unroll
        for (int i = 0; i < 2; i++)
            #pragma unroll
            for (int j = 0; j < 4; j++)
                #pragma unroll
                for (int e = 0; e < 4; e++) s[i][j][e] = 0.f;
        #pragma unroll
        for (int k8 = 0; k8 < 8; k8++) {
            u32 a[2][4], bb[4][2];
            #pragma unroll
            for (int i = 0; i < 2; i++) {
                const u32* p = Qs + (wm * 32 + 16 * i) * 72 + k8 * 8 + 2 * c4;
                uint2 lo = *(const uint2*)&p[r4 * 72];
                uint2 hi = *(const uint2*)&p[(r4 + 8) * 72];
                a[i][0] = lo.x; a[i][2] = lo.y;
                a[i][1] = hi.x; a[i][3] = hi.y;
            }
            #pragma unroll
            for (int j = 0; j < 4; j++) {
                uint2 kv = *(const uint2*)&Ks[(wn * 32 + 8 * j + r4) * 72 + k8 * 8 + 2 * c4];
                bb[j][0] = kv.x; bb[j][1] = kv.y;
            }
            #pragma unroll
            for (int i = 0; i < 2; i++)
                #pragma unroll
                for (int j = 0; j < 4; j++)
                    mma_tf32(s[i][j], a[i], bb[j]);
        }

        // ---- exp -> P (tf32, perm layout) + l of rounded values ----
        #pragma unroll
        for (int i = 0; i < 2; i++) {
            #pragma unroll
            for (int j = 0; j < 4; j++) {
                u32 t0 = to_tf32(__expf(s[i][j][0]));
                u32 t1 = to_tf32(__expf(s[i][j][1]));
                u32 t2 = to_tf32(__expf(s[i][j][2]));
                u32 t3 = to_tf32(__expf(s[i][j][3]));
                l[2 * i]     += __uint_as_float(t0) + __uint_as_float(t1);
                l[2 * i + 1] += __uint_as_float(t2) + __uint_as_float(t3);
                const int kblk = wn * 32 + 8 * j;
                u32* p0 = &Ps[(wm * 32 + 16 * i + r4) * 72 + kblk + pos];
                u32* p1 = &Ps[(wm * 32 + 16 * i + r4 + 8) * 72 + kblk + pos];
                p0[0] = t0; p0[2] = t1;
                p1[0] = t2; p1[2] = t3;
            }
        }
        __syncthreads();                    // Ks free; Ps visible

        if (ch < 15) {                      // K(ch+1) overlaps AV below
            const int kb = (ch + 1) * 64;
            #pragma unroll
            for (int r = 0; r < 4; r++) {
                int idx = r * 256 + tid;
                int row = idx >> 4, col = (idx & 15) << 2;
                cp16(KsA + (u32)(row * 72 + col) * 4, Kb + (size_t)(kb + row) * 64 + col);
            }
            CP_COMMIT();
            CP_WAIT1();                     // V(ch) done; K(ch+1) pending
        } else {
            CP_WAIT0();                     // V(15) done
        }
        __syncthreads();                    // V(ch) visible to all

        // ---- O += P @ V (paired frags) ----
        #pragma unroll
        for (int k8 = 0; k8 < 8; k8++) {
            u32 a[2][4], bb[4][2];
            #pragma unroll
            for (int i = 0; i < 2; i++) {
                const u32* p = Ps + (wm * 32 + 16 * i) * 72 + k8 * 8 + 2 * c4;
                uint2 lo = *(const uint2*)&p[r4 * 72];
                uint2 hi = *(const uint2*)&p[(r4 + 8) * 72];
                a[i][0] = lo.x; a[i][2] = lo.y;
                a[i][1] = hi.x; a[i][3] = hi.y;
            }
            #pragma unroll
            for (int j = 0; j < 4; j++) {
                uint2 vv = *(const uint2*)&Vs[(wn * 32 + 8 * j + r4) * 72 + k8 * 8 + 2 * c4];
                bb[j][0] = vv.x; bb[j][1] = vv.y;
            }
            #pragma unroll
            for (int i = 0; i < 2; i++)
                #pragma unroll
                for (int j = 0; j < 4; j++)
                    mma_tf32(o[i][j], a[i], bb[j]);
        }
        __syncthreads();                    // Vs free

        if (ch < 15) {                      // V(ch+1)
            const int kb = (ch + 1) * 64;
            #pragma unroll
            for (int r = 0; r < 4; r++) {
                int idx = r * 256 + tid;
                int row = idx >> 4, col = (idx & 15) << 2;
                cp16(VsA + (u32)(row * 72 + col) * 4, Vb + (size_t)row * HW + kb + col);
            }
            CP_COMMIT();
        }
    }

    // ---- l reduction (over c4 lanes, then across wn via smem atomics) ----
    #pragma unroll
    for (int e = 0; e < 4; e++) {
        float v = l[e];
        v += __shfl_xor_sync(0xffffffffu, v, 1);
        v += __shfl_xor_sync(0xffffffffu, v, 2);
        l[e] = v;
    }
    if (c4 == 0) {
        atomicAdd(&Lsum[wm * 32 + r4],          l[0]);
        atomicAdd(&Lsum[wm * 32 + r4 + 8],      l[1]);
        atomicAdd(&Lsum[wm * 32 + 16 + r4],     l[2]);
        atomicAdd(&Lsum[wm * 32 + 16 + r4 + 8], l[3]);
    }
    __syncthreads();

    // ---- O / l -> [b][c][q], tf32-rounded (feeds final projection) ----
    #pragma unroll
    for (int i = 0; i < 2; i++) {
        #pragma unroll
        for (int half = 0; half < 2; half++) {
            const int ql = wm * 32 + 16 * i + r4 + 8 * half;
            const float inv = 1.f / Lsum[ql];
            const int q = q0 + ql;
            #pragma unroll
            for (int j = 0; j < 4; j++) {
                const int c = h * 64 + wn * 32 + 8 * j + 2 * c4;
                const size_t base = ((size_t)(b * DIM + c)) * HW + q;
                O[base]      = rndf(o[i][j][2 * half] * inv);
                O[base + HW] = rndf(o[i][j][2 * half + 1] * inv);
            }
        }
    }
}

// ---------------------------------------------------------------------------
// kernel_launch
// inputs: a, b, Wq, bq, Wk, bk, Wv, bv, Wp, bp, gnA_w, gnA_b, gnB_w, gnB_b
// ---------------------------------------------------------------------------
extern "C" void kernel_launch(void* const* d_in, const int* in_sizes, int n_in,
                              void* d_out, int out_size) {
    (void)in_sizes; (void)n_in; (void)out_size;
    const float* a    = (const float*)d_in[0];
    const float* bIn  = (const float*)d_in[1];
    const float* Wq   = (const float*)d_in[2];
    const float* bq   = (const float*)d_in[3];
    const float* Wk   = (const float*)d_in[4];
    const float* bk   = (const float*)d_in[5];
    const float* Wv   = (const float*)d_in[6];
    const float* bv   = (const float*)d_in[7];
    const float* Wp   = (const float*)d_in[8];
    const float* bp   = (const float*)d_in[9];
    const float* gnAw = (const float*)d_in[10];
    const float* gnAb = (const float*)d_in[11];
    const float* gnBw = (const float*)d_in[12];
    const float* gnBb = (const float*)d_in[13];
    float* out = (float*)d_out;

    float *an, *bn, *q, *k, *v, *hb, *wbuf;
    cudaGetSymbolAddress((void**)&an, g_an);
    cudaGetSymbolAddress((void**)&bn, g_bn);
    cudaGetSymbolAddress((void**)&q,  g_q);
    cudaGetSymbolAddress((void**)&k,  g_k);
    cudaGetSymbolAddress((void**)&v,  g_v);
    cudaGetSymbolAddress((void**)&hb, g_h);
    cudaGetSymbolAddress((void**)&wbuf, g_w);

    const int PROJ_SMEM = (2 * 128 * 40 + 2 * 32 * 136) * 4;       // 75776 B
    const int ATTN_SMEM = (2 * 128 * 72 + 2 * 64 * 72) * 4;        // 110592 B
    cudaFuncSetAttribute((const void*)qkv_kernel,   cudaFuncAttributeMaxDynamicSharedMemorySize, PROJ_SMEM);
    cudaFuncSetAttribute((const void*)final_kernel, cudaFuncAttributeMaxDynamicSharedMemorySize, PROJ_SMEM);
    cudaFuncSetAttribute((const void*)attn_kernel,  cudaFuncAttributeMaxDynamicSharedMemorySize, ATTN_SMEM);

    wconv_kernel<<<dim3(64, 4), 256>>>(Wq, Wk, Wv, Wp, wbuf);

    gn_kernel<<<dim3(32, BATCH, 2), 256>>>(a, bIn, gnAw, gnAb, gnBw, gnBb, an, bn);

    qkv_kernel<<<dim3(HW / 128, DIM / 128, 3 * BATCH), 256, PROJ_SMEM>>>(
        wbuf, an, bn, bq, bk, bv, q, k, v);

    attn_kernel<<<dim3(HW / 128, HEADS, BATCH), 256, ATTN_SMEM>>>(q, k, v, hb);

    final_kernel<<<dim3(HW / 128, DIM / 128, BATCH), 256, PROJ_SMEM>>>(
        wbuf + 3 * DIM * DIM, hb, bp, bIn, out);
}

// round 14
// speedup vs baseline: 1.3543x; 1.2337x over previous
#include <cuda_runtime.h>
#include <cuda_fp16.h>
#include <cstdint>

typedef unsigned int u32;

#define BATCH 16
#define DIM   256
#define HW    1024
#define HEADS 4

// Scratch (allocation-free rule: __device__ globals)
__device__ float g_an[BATCH * DIM * HW];   // [b][c][q]  (tf32-rounded)
__device__ float g_bn[BATCH * DIM * HW];   // [b][c][q]  (tf32-rounded)
__device__ float g_q [BATCH * DIM * HW];   // [bh][q][d_perm] (x 1/16, rounded)
__device__ float g_k [BATCH * DIM * HW];   // [bh][q][d_perm] (rounded)
__device__ float g_v [BATCH * DIM * HW];   // fp16 [bh][d][key] (half the space used)
__device__ float g_h [BATCH * DIM * HW];   // [b][c][q]  (rounded)
__device__ float g_w [4 * DIM * DIM];      // rounded + k-permuted Wq,Wk,Wv,Wp

// ---------------------------------------------------------------------------
// Helpers
// ---------------------------------------------------------------------------
__device__ __forceinline__ void mma_tf32(float* d, const u32* a, const u32* b) {
    asm volatile(
        "mma.sync.aligned.m16n8k8.row.col.f32.tf32.tf32.f32 "
        "{%0,%1,%2,%3}, {%4,%5,%6,%7}, {%8,%9}, {%0,%1,%2,%3};"
        : "+f"(d[0]), "+f"(d[1]), "+f"(d[2]), "+f"(d[3])
        : "r"(a[0]), "r"(a[1]), "r"(a[2]), "r"(a[3]), "r"(b[0]), "r"(b[1]));
}
__device__ __forceinline__ void mma_f16(float* d, const u32* a, u32 b0, u32 b1) {
    asm volatile(
        "mma.sync.aligned.m16n8k16.row.col.f32.f16.f16.f32 "
        "{%0,%1,%2,%3}, {%4,%5,%6,%7}, {%8,%9}, {%0,%1,%2,%3};"
        : "+f"(d[0]), "+f"(d[1]), "+f"(d[2]), "+f"(d[3])
        : "r"(a[0]), "r"(a[1]), "r"(a[2]), "r"(a[3]), "r"(b0), "r"(b1));
}
__device__ __forceinline__ u32 to_tf32(float f) {
    u32 r; asm("cvt.rna.tf32.f32 %0, %1;" : "=r"(r) : "f"(f)); return r;
}
__device__ __forceinline__ float rndf(float f) { return __uint_as_float(to_tf32(f)); }
// pack {lo, hi} floats into one f16x2 register (lo in low half)
__device__ __forceinline__ u32 pack_f16(float lo, float hi) {
    u32 r; asm("cvt.rn.f16x2.f32 %0, %1, %2;" : "=r"(r) : "f"(hi), "f"(lo)); return r;
}
__device__ __forceinline__ u32 smem_u32(const void* p) {
    u32 a;
    asm("{ .reg .u64 t; cvta.to.shared.u64 t, %1; cvt.u32.u64 %0, t; }" : "=r"(a) : "l"(p));
    return a;
}
__device__ __forceinline__ void cp16(u32 dst, const float* src) {
    asm volatile("cp.async.cg.shared.global [%0], [%1], 16;" :: "r"(dst), "l"(src));
}
#define CP_COMMIT() asm volatile("cp.async.commit_group;")
#define CP_WAIT0()  asm volatile("cp.async.wait_group 0;")
#define CP_WAIT1()  asm volatile("cp.async.wait_group 1;")

// within-8-block pair permutation: x<4 -> 2x ; x>=4 -> 2x-7
__device__ __forceinline__ int perm8(int k) {
    int x = k & 7;
    return (k & ~7) + ((x < 4) ? (2 * x) : (2 * x - 7));
}

__inline__ __device__ float warpReduceSum(float v) {
    #pragma unroll
    for (int o = 16; o > 0; o >>= 1) v += __shfl_down_sync(0xffffffffu, v, o);
    return v;
}

// ---------------------------------------------------------------------------
// Weight pre-round + k-permute: g_w[y][m][perm(k)] = rna_tf32(W_y[m][k])
// ---------------------------------------------------------------------------
__global__ __launch_bounds__(256)
void wconv_kernel(const float* __restrict__ w0, const float* __restrict__ w1,
                  const float* __restrict__ w2, const float* __restrict__ w3,
                  float* __restrict__ out) {
    const float* s = (blockIdx.y == 0) ? w0 : (blockIdx.y == 1) ? w1
                   : (blockIdx.y == 2) ? w2 : w3;
    int i = (blockIdx.x * 256 + threadIdx.x) * 4;   // m*256 + k0 (k0 % 4 == 0)
    float4 v = *(const float4*)(s + i);
    float* ob = out + (size_t)blockIdx.y * DIM * DIM + (i & ~7) + ((i & 4) ? 1 : 0);
    ob[0] = rndf(v.x); ob[2] = rndf(v.y); ob[4] = rndf(v.z); ob[6] = rndf(v.w);
}

// ---------------------------------------------------------------------------
// GroupNorm (both tensors in one launch; z selects). [b][c][q] -> [b][c][q].
// ---------------------------------------------------------------------------
__global__ __launch_bounds__(256)
void gn_kernel(const float* __restrict__ xa, const float* __restrict__ xb,
               const float* __restrict__ gwA, const float* __restrict__ gbA,
               const float* __restrict__ gwB, const float* __restrict__ gbB,
               float* __restrict__ ya, float* __restrict__ yb) {
    const int g = blockIdx.x, b = blockIdx.y, t = threadIdx.x;
    const int which = blockIdx.z;
    const float* x = which ? xb : xa;
    const float* gamma = which ? gwB : gwA;
    const float* beta  = which ? gbB : gbA;
    float* y = which ? yb : ya;

    const int base = (b * DIM + g * 8) * HW;
    const float4* xp = (const float4*)(x + base);
    float4* yp = (float4*)(y + base);

    float4 r[8];
    float s = 0.f, s2 = 0.f;
    #pragma unroll
    for (int k = 0; k < 8; k++) {
        float4 v = xp[k * 256 + t];
        r[k] = v;
        s  += (v.x + v.y) + (v.z + v.w);
        s2 += (v.x * v.x + v.y * v.y) + (v.z * v.z + v.w * v.w);
    }
    s = warpReduceSum(s); s2 = warpReduceSum(s2);

    __shared__ float sh[2][8];
    int w = t >> 5, lane = t & 31;
    if (lane == 0) { sh[0][w] = s; sh[1][w] = s2; }
    __syncthreads();
    __shared__ float mu_s, inv_s;
    if (t == 0) {
        float S = 0.f, S2 = 0.f;
        #pragma unroll
        for (int i = 0; i < 8; i++) { S += sh[0][i]; S2 += sh[1][i]; }
        float mu = S * (1.0f / 8192.0f);
        float var = S2 * (1.0f / 8192.0f) - mu * mu;
        mu_s = mu; inv_s = rsqrtf(var + 1e-6f);
    }
    __syncthreads();
    const float mu = mu_s, inv = inv_s;

    #pragma unroll
    for (int k = 0; k < 8; k++) {
        int c = g * 8 + ((k * 256 + t) >> 8);
        float sc = inv * gamma[c];
        float shf = beta[c] - mu * sc;
        float4 v = r[k];
        v.x = rndf(v.x * sc + shf); v.y = rndf(v.y * sc + shf);
        v.z = rndf(v.z * sc + shf); v.w = rndf(v.w * sc + shf);
        yp[k * 256 + t] = v;
    }
}

// ---------------------------------------------------------------------------
// Shared GEMM core (mma.sync tf32, cp.async). CTA M=128 x N=128, K=256 in 8
// chunks of 32. 8 warps = 2(m) x 4(n). W is k-permuted -> A-frags are paired
// 64-bit LDS. Smem: Ws[m][k_perm] stride 40, Xs[k][n] stride 136.
// ---------------------------------------------------------------------------
struct ProjCtx {
    u32 smb;
    int tid, wid, lane, r4, c4, wm, wn;
};

__device__ __forceinline__ void proj_stage(const ProjCtx& cx, int ch,
                                           const float* W, const float* Xb,
                                           int m0, int n0) {
    const int k0 = ch * 32;
    const u32 wd = cx.smb + (u32)((ch & 1) ? 128 * 40 * 4 : 0);
    const u32 xd = cx.smb + (u32)(2 * 128 * 40 * 4 + ((ch & 1) ? 32 * 136 * 4 : 0));
    #pragma unroll
    for (int r = 0; r < 4; r++) {
        int idx = r * 256 + cx.tid;
        int row = idx >> 3, col = (idx & 7) << 2;
        cp16(wd + (u32)(row * 40 + col) * 4, W + (size_t)(m0 + row) * DIM + k0 + col);
    }
    #pragma unroll
    for (int r = 0; r < 4; r++) {
        int idx = r * 256 + cx.tid;
        int row = idx >> 5, col = (idx & 31) << 2;
        cp16(xd + (u32)(row * 136 + col) * 4, Xb + (size_t)(k0 + row) * HW + n0 + col);
    }
    CP_COMMIT();
}

__device__ __forceinline__ void proj_mainloop(const ProjCtx& cx, const u32* dsm,
                                              const float* W, const float* Xb,
                                              int m0, int n0, float d[4][4][4]) {
    proj_stage(cx, 0, W, Xb, m0, n0);
    for (int ch = 0; ch < 8; ch++) {
        if (ch < 7) { proj_stage(cx, ch + 1, W, Xb, m0, n0); CP_WAIT1(); } else { CP_WAIT0(); }
        __syncthreads();
        const u32* Ws = dsm + ((ch & 1) ? 128 * 40 : 0);
        const u32* Xs = dsm + 2 * 128 * 40 + ((ch & 1) ? 32 * 136 : 0);
        #pragma unroll
        for (int k8 = 0; k8 < 4; k8++) {
            u32 a[4][4], bb[4][2];
            #pragma unroll
            for (int i = 0; i < 4; i++) {
                const u32* p = Ws + (cx.wm * 64 + 16 * i) * 40 + k8 * 8 + 2 * cx.c4;
                uint2 lo = *(const uint2*)&p[cx.r4 * 40];
                uint2 hi = *(const uint2*)&p[(cx.r4 + 8) * 40];
                a[i][0] = lo.x; a[i][2] = lo.y;
                a[i][1] = hi.x; a[i][3] = hi.y;
            }
            #pragma unroll
            for (int j = 0; j < 4; j++) {
                const u32* p = Xs + k8 * 8 * 136 + cx.wn * 32 + 8 * j + cx.r4;
                bb[j][0] = p[cx.c4 * 136];
                bb[j][1] = p[(cx.c4 + 4) * 136];
            }
            #pragma unroll
            for (int i = 0; i < 4; i++)
                #pragma unroll
                for (int j = 0; j < 4; j++)
                    mma_tf32(d[i][j], a[i], bb[j]);
        }
        __syncthreads();
    }
}

// ---------------------------------------------------------------------------
// QKV projection, one launch: z = proj*16 + b.
// proj 0 = Q -> [bh][q][d_perm] x(1/16); 1 = K -> [bh][q][d_perm];
// proj 2 = V -> fp16 [bh][d][key] (natural key order, f16x2 stores).
// ---------------------------------------------------------------------------
__global__ __launch_bounds__(256, 2)
void qkv_kernel(const float* __restrict__ wbuf,
                const float* __restrict__ an, const float* __restrict__ bn,
                const float* __restrict__ bq, const float* __restrict__ bk,
                const float* __restrict__ bv,
                float* __restrict__ Yq, float* __restrict__ Yk, float* __restrict__ Yv) {
    extern __shared__ u32 dsm[];
    ProjCtx cx;
    cx.smb = smem_u32(dsm);
    cx.tid = threadIdx.x; cx.wid = cx.tid >> 5; cx.lane = cx.tid & 31;
    cx.r4 = cx.lane >> 2; cx.c4 = cx.lane & 3;
    cx.wm = cx.wid >> 2; cx.wn = cx.wid & 3;

    const int pz = blockIdx.z >> 4;        // 0=Q 1=K 2=V
    const int b  = blockIdx.z & 15;
    const int n0 = blockIdx.x * 128, m0 = blockIdx.y * 128;
    const float* W  = wbuf + (size_t)pz * DIM * DIM;
    const float* Xb = ((pz == 0) ? bn : an) + (size_t)b * DIM * HW;
    const float* bias = (pz == 0) ? bq : (pz == 1) ? bk : bv;
    float* Y = (pz == 0) ? Yq : (pz == 1) ? Yk : Yv;

    float d[4][4][4];
    #pragma unroll
    for (int i = 0; i < 4; i++)
        #pragma unroll
        for (int j = 0; j < 4; j++)
            #pragma unroll
            for (int e = 0; e < 4; e++) d[i][j][e] = 0.f;

    proj_mainloop(cx, dsm, W, Xb, m0, n0, d);

    const float sc = (pz == 0) ? 0.0625f : 1.0f;
    #pragma unroll
    for (int i = 0; i < 4; i++) {
        #pragma unroll
        for (int half = 0; half < 2; half++) {
            const int m = m0 + cx.wm * 64 + 16 * i + cx.r4 + 8 * half;
            const float bvv = bias[m];
            const int hh = m >> 6, dd = m & 63;
            if (pz == 2) {
                // V: fp16 [bh][d][key]
                __half* Yh = (__half*)Y + (((size_t)(b * HEADS + hh)) << 16) + (size_t)dd * HW;
                #pragma unroll
                for (int j = 0; j < 4; j++) {
                    const int n = n0 + cx.wn * 32 + 8 * j + 2 * cx.c4;
                    u32 pk = pack_f16(d[i][j][2 * half] + bvv, d[i][j][2 * half + 1] + bvv);
                    *(u32*)(Yh + n) = pk;
                }
            } else {
                // Q/K: [bh][q][d_perm]
                const int ddp = perm8(dd);
                float* Yh = Y + ((size_t)(b * HEADS + hh) << 16) + ddp;
                #pragma unroll
                for (int j = 0; j < 4; j++) {
                    const int n = n0 + cx.wn * 32 + 8 * j + 2 * cx.c4;
                    Yh[(size_t)n * 64]       = rndf((d[i][j][2 * half] + bvv) * sc);
                    Yh[(size_t)(n + 1) * 64] = rndf((d[i][j][2 * half + 1] + bvv) * sc);
                }
            }
        }
    }
}

// ---------------------------------------------------------------------------
// Final projection: out[b][m][q] = (Wp @ h + bias + skip) / sqrt(2)
// ---------------------------------------------------------------------------
__global__ __launch_bounds__(256, 2)
void final_kernel(const float* __restrict__ W, const float* __restrict__ X,
                  const float* __restrict__ bias, const float* __restrict__ skip,
                  float* __restrict__ Y) {
    extern __shared__ u32 dsm[];
    ProjCtx cx;
    cx.smb = smem_u32(dsm);
    cx.tid = threadIdx.x; cx.wid = cx.tid >> 5; cx.lane = cx.tid & 31;
    cx.r4 = cx.lane >> 2; cx.c4 = cx.lane & 3;
    cx.wm = cx.wid >> 2; cx.wn = cx.wid & 3;

    const int n0 = blockIdx.x * 128, m0 = blockIdx.y * 128, b = blockIdx.z;
    const float* Xb = X + (size_t)b * DIM * HW;

    float d[4][4][4];
    #pragma unroll
    for (int i = 0; i < 4; i++)
        #pragma unroll
        for (int j = 0; j < 4; j++)
            #pragma unroll
            for (int e = 0; e < 4; e++) d[i][j][e] = 0.f;

    proj_mainloop(cx, dsm, W, Xb, m0, n0, d);

    const float r2 = 0.7071067811865476f;
    #pragma unroll
    for (int i = 0; i < 4; i++) {
        #pragma unroll
        for (int half = 0; half < 2; half++) {
            const int m = m0 + cx.wm * 64 + 16 * i + cx.r4 + 8 * half;
            const float bvv = bias[m];
            const size_t rowb = ((size_t)b * DIM + m) * HW;
            #pragma unroll
            for (int j = 0; j < 4; j++) {
                const int n = n0 + cx.wn * 32 + 8 * j + 2 * cx.c4;
                float2 sk = *(const float2*)(skip + rowb + n);
                float2 v = make_float2((d[i][j][2 * half] + bvv + sk.x) * r2,
                                       (d[i][j][2 * half + 1] + bvv + sk.y) * r2);
                *(float2*)(Y + rowb + n) = v;
            }
        }
    }
}

// ---------------------------------------------------------------------------
// Attention. CTA = (128 q, head, batch), 256 threads = 8 warps x 16q each;
// every warp spans the FULL 64-key chunk -> P lives in registers as fp16
// AV A-fragments (exp output packs directly; no smem round-trip, no Lsum).
// S: tf32 (Q,K paired-k).  AV: fp16 m16n8k16 (V fp16 in smem).
// Smem: Qs[128][72] u32, Ks[2][64][72] u32, Vs[2][64][36] u32 = 92160 B.
// Double-buffered K/V; ONE __syncthreads per chunk (wait->sync->issue->compute).
// ---------------------------------------------------------------------------
__global__ __launch_bounds__(256, 2)
void attn_kernel(const float* __restrict__ Qg, const float* __restrict__ Kg,
                 const float* __restrict__ Vg, float* __restrict__ O) {
    extern __shared__ u32 dsm[];
    const u32 smb = smem_u32(dsm);
    const u32 QsA = smb;
    const u32 KsA = smb + 128 * 72 * 4;
    const u32 VsA = KsA + 2 * 64 * 72 * 4;
    const u32* Qs = dsm;                        // [q][d_perm] stride 72
    const u32* Ksb0 = dsm + 128 * 72;           // 2 x [key][d_perm] stride 72
    const u32* Vsb0 = dsm + 128 * 72 + 2 * 64 * 72;  // 2 x [d][key_pair] stride 36

    const int tid = threadIdx.x;
    const int wid = tid >> 5, lane = tid & 31;
    const int r4 = lane >> 2, c4 = lane & 3;
    const int q0 = blockIdx.x * 128;
    const int h = blockIdx.y, b = blockIdx.z;
    const int bh = b * HEADS + h;
    const float* Qb = Qg + ((size_t)bh << 16);           // [q][d_perm]
    const float* Kb = Kg + ((size_t)bh << 16);           // [key][d_perm]
    const __half* Vb = (const __half*)Vg + ((size_t)bh << 16);   // [d][key]

    auto stageKV = [&](int ch) {
        const int kb = ch * 64;
        const u32 kd = KsA + (u32)((ch & 1) * 64 * 72 * 4);
        const u32 vd = VsA + (u32)((ch & 1) * 64 * 36 * 4);
        #pragma unroll
        for (int r = 0; r < 4; r++) {
            int idx = r * 256 + tid;
            int row = idx >> 4, col = (idx & 15) << 2;
            cp16(kd + (u32)(row * 72 + col) * 4, Kb + (size_t)(kb + row) * 64 + col);
        }
        #pragma unroll
        for (int r = 0; r < 2; r++) {
            int idx = r * 256 + tid;
            int row = idx >> 3, c16 = idx & 7;
            cp16(vd + (u32)(row * 36 + c16 * 4) * 4,
                 (const float*)(Vb + (size_t)row * HW + kb + c16 * 8));
        }
        CP_COMMIT();
    };

    // prologue: Q (once) + chunk 0 K/V as one group
    #pragma unroll
    for (int r = 0; r < 8; r++) {
        int idx = r * 256 + tid;
        int row = idx >> 4, col = (idx & 15) << 2;
        cp16(QsA + (u32)(row * 72 + col) * 4, Qb + (size_t)(q0 + row) * 64 + col);
    }
    #pragma unroll
    for (int r = 0; r < 4; r++) {
        int idx = r * 256 + tid;
        int row = idx >> 4, col = (idx & 15) << 2;
        cp16(KsA + (u32)(row * 72 + col) * 4, Kb + (size_t)row * 64 + col);
    }
    #pragma unroll
    for (int r = 0; r < 2; r++) {
        int idx = r * 256 + tid;
        int row = idx >> 3, c16 = idx & 7;
        cp16(VsA + (u32)(row * 36 + c16 * 4) * 4,
             (const float*)(Vb + (size_t)row * HW + c16 * 8));
    }
    CP_COMMIT();

    float o[8][4];
    #pragma unroll
    for (int j = 0; j < 8; j++)
        #pragma unroll
        for (int e = 0; e < 4; e++) o[j][e] = 0.f;
    float l0 = 0.f, l1 = 0.f;

    const u32* qbase = Qs + (wid * 16) * 72;

    for (int ch = 0; ch < 16; ch++) {
        CP_WAIT0();             // chunk ch landed (thread-local)
        __syncthreads();        // visible to all; all warps done with prior chunk
        if (ch < 15) stageKV(ch + 1);   // flies during this chunk's compute

        const u32* Ks = Ksb0 + (ch & 1) * 64 * 72;
        const u32* Vs = Vsb0 + (ch & 1) * 64 * 36;

        // ---- S = Q @ K^T (tf32, warp = 16q x 64key) ----
        float s[8][4];
        #pragma unroll
        for (int j = 0; j < 8; j++)
            #pragma unroll
            for (int e = 0; e < 4; e++) s[j][e] = 0.f;
        #pragma unroll
        for (int k8 = 0; k8 < 8; k8++) {
            u32 a[4];
            {
                const u32* p = qbase + k8 * 8 + 2 * c4;
                uint2 lo = *(const uint2*)&p[r4 * 72];
                uint2 hi = *(const uint2*)&p[(r4 + 8) * 72];
                a[0] = lo.x; a[2] = lo.y;
                a[1] = hi.x; a[3] = hi.y;
            }
            #pragma unroll
            for (int j = 0; j < 8; j++) {
                uint2 kv = *(const uint2*)&Ks[(8 * j + r4) * 72 + k8 * 8 + 2 * c4];
                u32 bb[2] = { kv.x, kv.y };
                mma_tf32(s[j], a, bb);
            }
        }

        // ---- exp -> fp16 AV A-fragments (registers; no smem, no shuffle) ----
        u32 af[4][4];
        #pragma unroll
        for (int t = 0; t < 4; t++) {
            float e0a = __expf(s[2 * t][0]),     e1a = __expf(s[2 * t][1]);
            float e2a = __expf(s[2 * t][2]),     e3a = __expf(s[2 * t][3]);
            float e0b = __expf(s[2 * t + 1][0]), e1b = __expf(s[2 * t + 1][1]);
            float e2b = __expf(s[2 * t + 1][2]), e3b = __expf(s[2 * t + 1][3]);
            l0 += (e0a + e1a) + (e0b + e1b);
            l1 += (e2a + e3a) + (e2b + e3b);
            af[t][0] = pack_f16(e0a, e1a);   // rows r4,   k 16t+2c4..+1
            af[t][1] = pack_f16(e2a, e3a);   // rows r4+8, same k
            af[t][2] = pack_f16(e0b, e1b);   // rows r4,   k 16t+8+2c4..+1
            af[t][3] = pack_f16(e2b, e3b);   // rows r4+8
        }

        // ---- O += P @ V (fp16 m16n8k16; B from Vs [d][key_pair] s36) ----
        #pragma unroll
        for (int t = 0; t < 4; t++) {
            #pragma unroll
            for (int j = 0; j < 8; j++) {
                const u32* p = Vs + (8 * j + r4) * 36 + t * 8;
                mma_f16(o[j], af[t], p[c4], p[c4 + 4]);
            }
        }
    }

    // ---- l reduction within 4-lane groups only (warp owns its q rows) ----
    l0 += __shfl_xor_sync(0xffffffffu, l0, 1);
    l0 += __shfl_xor_sync(0xffffffffu, l0, 2);
    l1 += __shfl_xor_sync(0xffffffffu, l1, 1);
    l1 += __shfl_xor_sync(0xffffffffu, l1, 2);
    const float inv0 = 1.f / l0, inv1 = 1.f / l1;

    // ---- O / l -> [b][c][q], tf32-rounded (feeds final projection) ----
    const int qrow = q0 + wid * 16 + r4;
    #pragma unroll
    for (int j = 0; j < 8; j++) {
        const int c = h * 64 + 8 * j + 2 * c4;
        const size_t base = ((size_t)(b * DIM + c)) * HW + qrow;
        O[base]          = rndf(o[j][0] * inv0);
        O[base + HW]     = rndf(o[j][1] * inv0);
        O[base + 8]      = rndf(o[j][2] * inv1);
        O[base + HW + 8] = rndf(o[j][3] * inv1);
    }
}

// ---------------------------------------------------------------------------
// kernel_launch
// inputs: a, b, Wq, bq, Wk, bk, Wv, bv, Wp, bp, gnA_w, gnA_b, gnB_w, gnB_b
// ---------------------------------------------------------------------------
extern "C" void kernel_launch(void* const* d_in, const int* in_sizes, int n_in,
                              void* d_out, int out_size) {
    (void)in_sizes; (void)n_in; (void)out_size;
    const float* a    = (const float*)d_in[0];
    const float* bIn  = (const float*)d_in[1];
    const float* Wq   = (const float*)d_in[2];
    const float* bq   = (const float*)d_in[3];
    const float* Wk   = (const float*)d_in[4];
    const float* bk   = (const float*)d_in[5];
    const float* Wv   = (const float*)d_in[6];
    const float* bv   = (const float*)d_in[7];
    const float* Wp   = (const float*)d_in[8];
    const float* bp   = (const float*)d_in[9];
    const float* gnAw = (const float*)d_in[10];
    const float* gnAb = (const float*)d_in[11];
    const float* gnBw = (const float*)d_in[12];
    const float* gnBb = (const float*)d_in[13];
    float* out = (float*)d_out;

    float *an, *bn, *q, *k, *v, *hb, *wbuf;
    cudaGetSymbolAddress((void**)&an, g_an);
    cudaGetSymbolAddress((void**)&bn, g_bn);
    cudaGetSymbolAddress((void**)&q,  g_q);
    cudaGetSymbolAddress((void**)&k,  g_k);
    cudaGetSymbolAddress((void**)&v,  g_v);
    cudaGetSymbolAddress((void**)&hb, g_h);
    cudaGetSymbolAddress((void**)&wbuf, g_w);

    const int PROJ_SMEM = (2 * 128 * 40 + 2 * 32 * 136) * 4;       // 75776 B
    const int ATTN_SMEM = (128 * 72 + 2 * 64 * 72 + 2 * 64 * 36) * 4;  // 92160 B
    cudaFuncSetAttribute((const void*)qkv_kernel,   cudaFuncAttributeMaxDynamicSharedMemorySize, PROJ_SMEM);
    cudaFuncSetAttribute((const void*)final_kernel, cudaFuncAttributeMaxDynamicSharedMemorySize, PROJ_SMEM);
    cudaFuncSetAttribute((const void*)attn_kernel,  cudaFuncAttributeMaxDynamicSharedMemorySize, ATTN_SMEM);

    wconv_kernel<<<dim3(64, 4), 256>>>(Wq, Wk, Wv, Wp, wbuf);

    gn_kernel<<<dim3(32, BATCH, 2), 256>>>(a, bIn, gnAw, gnAb, gnBw, gnBb, an, bn);

    qkv_kernel<<<dim3(HW / 128, DIM / 128, 3 * BATCH), 256, PROJ_SMEM>>>(
        wbuf, an, bn, bq, bk, bv, q, k, v);

    attn_kernel<<<dim3(HW / 128, HEADS, BATCH), 256, ATTN_SMEM>>>(q, k, v, hb);

    final_kernel<<<dim3(HW / 128, DIM / 128, BATCH), 256, PROJ_SMEM>>>(
        wbuf + 3 * DIM * DIM, hb, bp, bIn, out);
}

// round 17
// speedup vs baseline: 1.5627x; 1.1539x over previous
#include <cuda_runtime.h>
#include <cuda_fp16.h>
#include <cstdint>

typedef unsigned int u32;

#define BATCH 16
#define DIM   256
#define HW    1024
#define HEADS 4

// Scratch (allocation-free rule: __device__ globals)
__device__ float g_an[BATCH * DIM * HW];   // [b][c][q]  (tf32-rounded)
__device__ float g_bn[BATCH * DIM * HW];   // [b][c][q]  (tf32-rounded)
__device__ float g_q [BATCH * DIM * HW];   // fp16 [bh][q][d] (x 1/16)
__device__ float g_k [BATCH * DIM * HW];   // fp16 [bh][q][d]
__device__ float g_v [BATCH * DIM * HW];   // fp16 [bh][d][key]
__device__ float g_h [BATCH * DIM * HW];   // [b][c][q]  (tf32-rounded)
__device__ float g_w [4 * DIM * DIM];      // rounded + k-permuted Wq,Wk,Wv,Wp

// ---------------------------------------------------------------------------
// Helpers
// ---------------------------------------------------------------------------
__device__ __forceinline__ void mma_tf32(float* d, const u32* a, const u32* b) {
    asm volatile(
        "mma.sync.aligned.m16n8k8.row.col.f32.tf32.tf32.f32 "
        "{%0,%1,%2,%3}, {%4,%5,%6,%7}, {%8,%9}, {%0,%1,%2,%3};"
        : "+f"(d[0]), "+f"(d[1]), "+f"(d[2]), "+f"(d[3])
        : "r"(a[0]), "r"(a[1]), "r"(a[2]), "r"(a[3]), "r"(b[0]), "r"(b[1]));
}
__device__ __forceinline__ void mma_f16(float* d, const u32* a, u32 b0, u32 b1) {
    asm volatile(
        "mma.sync.aligned.m16n8k16.row.col.f32.f16.f16.f32 "
        "{%0,%1,%2,%3}, {%4,%5,%6,%7}, {%8,%9}, {%0,%1,%2,%3};"
        : "+f"(d[0]), "+f"(d[1]), "+f"(d[2]), "+f"(d[3])
        : "r"(a[0]), "r"(a[1]), "r"(a[2]), "r"(a[3]), "r"(b0), "r"(b1));
}
__device__ __forceinline__ u32 to_tf32(float f) {
    u32 r; asm("cvt.rna.tf32.f32 %0, %1;" : "=r"(r) : "f"(f)); return r;
}
__device__ __forceinline__ float rndf(float f) { return __uint_as_float(to_tf32(f)); }
// pack {lo, hi} floats into one f16x2 register (lo in low half)
__device__ __forceinline__ u32 pack_f16(float lo, float hi) {
    u32 r; asm("cvt.rn.f16x2.f32 %0, %1, %2;" : "=r"(r) : "f"(hi), "f"(lo)); return r;
}
__device__ __forceinline__ u32 smem_u32(const void* p) {
    u32 a;
    asm("{ .reg .u64 t; cvta.to.shared.u64 t, %1; cvt.u32.u64 %0, t; }" : "=r"(a) : "l"(p));
    return a;
}
__device__ __forceinline__ void cp16(u32 dst, const void* src) {
    asm volatile("cp.async.cg.shared.global [%0], [%1], 16;" :: "r"(dst), "l"(src));
}
#define CP_COMMIT() asm volatile("cp.async.commit_group;")
#define CP_WAIT0()  asm volatile("cp.async.wait_group 0;")
#define CP_WAIT1()  asm volatile("cp.async.wait_group 1;")

__inline__ __device__ float warpReduceSum(float v) {
    #pragma unroll
    for (int o = 16; o > 0; o >>= 1) v += __shfl_down_sync(0xffffffffu, v, o);
    return v;
}

// ---------------------------------------------------------------------------
// Weight pre-round + k-permute: g_w[y][m][perm(k)] = rna_tf32(W_y[m][k])
// (pairing for the tf32 projection GEMM's A-fragments)
// ---------------------------------------------------------------------------
__global__ __launch_bounds__(256)
void wconv_kernel(const float* __restrict__ w0, const float* __restrict__ w1,
                  const float* __restrict__ w2, const float* __restrict__ w3,
                  float* __restrict__ out) {
    const float* s = (blockIdx.y == 0) ? w0 : (blockIdx.y == 1) ? w1
                   : (blockIdx.y == 2) ? w2 : w3;
    int i = (blockIdx.x * 256 + threadIdx.x) * 4;   // m*256 + k0 (k0 % 4 == 0)
    float4 v = *(const float4*)(s + i);
    float* ob = out + (size_t)blockIdx.y * DIM * DIM + (i & ~7) + ((i & 4) ? 1 : 0);
    ob[0] = rndf(v.x); ob[2] = rndf(v.y); ob[4] = rndf(v.z); ob[6] = rndf(v.w);
}

// ---------------------------------------------------------------------------
// GroupNorm (both tensors in one launch; z selects). [b][c][q] -> [b][c][q].
// ---------------------------------------------------------------------------
__global__ __launch_bounds__(256)
void gn_kernel(const float* __restrict__ xa, const float* __restrict__ xb,
               const float* __restrict__ gwA, const float* __restrict__ gbA,
               const float* __restrict__ gwB, const float* __restrict__ gbB,
               float* __restrict__ ya, float* __restrict__ yb) {
    const int g = blockIdx.x, b = blockIdx.y, t = threadIdx.x;
    const int which = blockIdx.z;
    const float* x = which ? xb : xa;
    const float* gamma = which ? gwB : gwA;
    const float* beta  = which ? gbB : gbA;
    float* y = which ? yb : ya;

    const int base = (b * DIM + g * 8) * HW;
    const float4* xp = (const float4*)(x + base);
    float4* yp = (float4*)(y + base);

    float4 r[8];
    float s = 0.f, s2 = 0.f;
    #pragma unroll
    for (int k = 0; k < 8; k++) {
        float4 v = xp[k * 256 + t];
        r[k] = v;
        s  += (v.x + v.y) + (v.z + v.w);
        s2 += (v.x * v.x + v.y * v.y) + (v.z * v.z + v.w * v.w);
    }
    s = warpReduceSum(s); s2 = warpReduceSum(s2);

    __shared__ float sh[2][8];
    int w = t >> 5, lane = t & 31;
    if (lane == 0) { sh[0][w] = s; sh[1][w] = s2; }
    __syncthreads();
    __shared__ float mu_s, inv_s;
    if (t == 0) {
        float S = 0.f, S2 = 0.f;
        #pragma unroll
        for (int i = 0; i < 8; i++) { S += sh[0][i]; S2 += sh[1][i]; }
        float mu = S * (1.0f / 8192.0f);
        float var = S2 * (1.0f / 8192.0f) - mu * mu;
        mu_s = mu; inv_s = rsqrtf(var + 1e-6f);
    }
    __syncthreads();
    const float mu = mu_s, inv = inv_s;

    #pragma unroll
    for (int k = 0; k < 8; k++) {
        int c = g * 8 + ((k * 256 + t) >> 8);
        float sc = inv * gamma[c];
        float shf = beta[c] - mu * sc;
        float4 v = r[k];
        v.x = rndf(v.x * sc + shf); v.y = rndf(v.y * sc + shf);
        v.z = rndf(v.z * sc + shf); v.w = rndf(v.w * sc + shf);
        yp[k * 256 + t] = v;
    }
}

// ---------------------------------------------------------------------------
// Shared GEMM core (mma.sync tf32, cp.async). CTA M=128 x N=128, K=256 in 8
// chunks of 32. 8 warps = 2(m) x 4(n). W is k-permuted -> A-frags are paired
// 64-bit LDS. Smem: Ws[m][k_perm] stride 40, Xs[k][n] stride 136.
// ---------------------------------------------------------------------------
struct ProjCtx {
    u32 smb;
    int tid, wid, lane, r4, c4, wm, wn;
};

__device__ __forceinline__ void proj_stage(const ProjCtx& cx, int ch,
                                           const float* W, const float* Xb,
                                           int m0, int n0) {
    const int k0 = ch * 32;
    const u32 wd = cx.smb + (u32)((ch & 1) ? 128 * 40 * 4 : 0);
    const u32 xd = cx.smb + (u32)(2 * 128 * 40 * 4 + ((ch & 1) ? 32 * 136 * 4 : 0));
    #pragma unroll
    for (int r = 0; r < 4; r++) {
        int idx = r * 256 + cx.tid;
        int row = idx >> 3, col = (idx & 7) << 2;
        cp16(wd + (u32)(row * 40 + col) * 4, W + (size_t)(m0 + row) * DIM + k0 + col);
    }
    #pragma unroll
    for (int r = 0; r < 4; r++) {
        int idx = r * 256 + cx.tid;
        int row = idx >> 5, col = (idx & 31) << 2;
        cp16(xd + (u32)(row * 136 + col) * 4, Xb + (size_t)(k0 + row) * HW + n0 + col);
    }
    CP_COMMIT();
}

__device__ __forceinline__ void proj_mainloop(const ProjCtx& cx, const u32* dsm,
                                              const float* W, const float* Xb,
                                              int m0, int n0, float d[4][4][4]) {
    proj_stage(cx, 0, W, Xb, m0, n0);
    for (int ch = 0; ch < 8; ch++) {
        if (ch < 7) { proj_stage(cx, ch + 1, W, Xb, m0, n0); CP_WAIT1(); } else { CP_WAIT0(); }
        __syncthreads();
        const u32* Ws = dsm + ((ch & 1) ? 128 * 40 : 0);
        const u32* Xs = dsm + 2 * 128 * 40 + ((ch & 1) ? 32 * 136 : 0);
        #pragma unroll
        for (int k8 = 0; k8 < 4; k8++) {
            u32 a[4][4], bb[4][2];
            #pragma unroll
            for (int i = 0; i < 4; i++) {
                const u32* p = Ws + (cx.wm * 64 + 16 * i) * 40 + k8 * 8 + 2 * cx.c4;
                uint2 lo = *(const uint2*)&p[cx.r4 * 40];
                uint2 hi = *(const uint2*)&p[(cx.r4 + 8) * 40];
                a[i][0] = lo.x; a[i][2] = lo.y;
                a[i][1] = hi.x; a[i][3] = hi.y;
            }
            #pragma unroll
            for (int j = 0; j < 4; j++) {
                const u32* p = Xs + k8 * 8 * 136 + cx.wn * 32 + 8 * j + cx.r4;
                bb[j][0] = p[cx.c4 * 136];
                bb[j][1] = p[(cx.c4 + 4) * 136];
            }
            #pragma unroll
            for (int i = 0; i < 4; i++)
                #pragma unroll
                for (int j = 0; j < 4; j++)
                    mma_tf32(d[i][j], a[i], bb[j]);
        }
        __syncthreads();
    }
}

// ---------------------------------------------------------------------------
// QKV projection, one launch: z = proj*16 + b.
// proj 0 = Q -> fp16 [bh][q][d] x(1/16); 1 = K -> fp16 [bh][q][d];
// proj 2 = V -> fp16 [bh][d][key].
// ---------------------------------------------------------------------------
__global__ __launch_bounds__(256, 2)
void qkv_kernel(const float* __restrict__ wbuf,
                const float* __restrict__ an, const float* __restrict__ bn,
                const float* __restrict__ bq, const float* __restrict__ bk,
                const float* __restrict__ bv,
                float* __restrict__ Yq, float* __restrict__ Yk, float* __restrict__ Yv) {
    extern __shared__ u32 dsm[];
    ProjCtx cx;
    cx.smb = smem_u32(dsm);
    cx.tid = threadIdx.x; cx.wid = cx.tid >> 5; cx.lane = cx.tid & 31;
    cx.r4 = cx.lane >> 2; cx.c4 = cx.lane & 3;
    cx.wm = cx.wid >> 2; cx.wn = cx.wid & 3;

    const int pz = blockIdx.z >> 4;        // 0=Q 1=K 2=V
    const int b  = blockIdx.z & 15;
    const int n0 = blockIdx.x * 128, m0 = blockIdx.y * 128;
    const float* W  = wbuf + (size_t)pz * DIM * DIM;
    const float* Xb = ((pz == 0) ? bn : an) + (size_t)b * DIM * HW;
    const float* bias = (pz == 0) ? bq : (pz == 1) ? bk : bv;
    float* Y = (pz == 0) ? Yq : (pz == 1) ? Yk : Yv;

    float d[4][4][4];
    #pragma unroll
    for (int i = 0; i < 4; i++)
        #pragma unroll
        for (int j = 0; j < 4; j++)
            #pragma unroll
            for (int e = 0; e < 4; e++) d[i][j][e] = 0.f;

    proj_mainloop(cx, dsm, W, Xb, m0, n0, d);

    const float sc = (pz == 0) ? 0.0625f : 1.0f;
    #pragma unroll
    for (int i = 0; i < 4; i++) {
        #pragma unroll
        for (int half = 0; half < 2; half++) {
            const int m = m0 + cx.wm * 64 + 16 * i + cx.r4 + 8 * half;
            const float bvv = bias[m];
            const int hh = m >> 6, dd = m & 63;
            if (pz == 2) {
                // V: fp16 [bh][d][key]
                __half* Yh = (__half*)Y + (((size_t)(b * HEADS + hh)) << 16) + (size_t)dd * HW;
                #pragma unroll
                for (int j = 0; j < 4; j++) {
                    const int n = n0 + cx.wn * 32 + 8 * j + 2 * cx.c4;
                    u32 pk = pack_f16(d[i][j][2 * half] + bvv, d[i][j][2 * half + 1] + bvv);
                    *(u32*)(Yh + n) = pk;
                }
            } else {
                // Q/K: fp16 [bh][q][d]
                __half* Yh = (__half*)Y + (((size_t)(b * HEADS + hh)) << 16) + dd;
                #pragma unroll
                for (int j = 0; j < 4; j++) {
                    const int n = n0 + cx.wn * 32 + 8 * j + 2 * cx.c4;
                    Yh[(size_t)n * 64]       = __float2half_rn((d[i][j][2 * half] + bvv) * sc);
                    Yh[(size_t)(n + 1) * 64] = __float2half_rn((d[i][j][2 * half + 1] + bvv) * sc);
                }
            }
        }
    }
}

// ---------------------------------------------------------------------------
// Final projection: out[b][m][q] = (Wp @ h + bias + skip) / sqrt(2)
// ---------------------------------------------------------------------------
__global__ __launch_bounds__(256, 2)
void final_kernel(const float* __restrict__ W, const float* __restrict__ X,
                  const float* __restrict__ bias, const float* __restrict__ skip,
                  float* __restrict__ Y) {
    extern __shared__ u32 dsm[];
    ProjCtx cx;
    cx.smb = smem_u32(dsm);
    cx.tid = threadIdx.x; cx.wid = cx.tid >> 5; cx.lane = cx.tid & 31;
    cx.r4 = cx.lane >> 2; cx.c4 = cx.lane & 3;
    cx.wm = cx.wid >> 2; cx.wn = cx.wid & 3;

    const int n0 = blockIdx.x * 128, m0 = blockIdx.y * 128, b = blockIdx.z;
    const float* Xb = X + (size_t)b * DIM * HW;

    float d[4][4][4];
    #pragma unroll
    for (int i = 0; i < 4; i++)
        #pragma unroll
        for (int j = 0; j < 4; j++)
            #pragma unroll
            for (int e = 0; e < 4; e++) d[i][j][e] = 0.f;

    proj_mainloop(cx, dsm, W, Xb, m0, n0, d);

    const float r2 = 0.7071067811865476f;
    #pragma unroll
    for (int i = 0; i < 4; i++) {
        #pragma unroll
        for (int half = 0; half < 2; half++) {
            const int m = m0 + cx.wm * 64 + 16 * i + cx.r4 + 8 * half;
            const float bvv = bias[m];
            const size_t rowb = ((size_t)b * DIM + m) * HW;
            #pragma unroll
            for (int j = 0; j < 4; j++) {
                const int n = n0 + cx.wn * 32 + 8 * j + 2 * cx.c4;
                float2 sk = *(const float2*)(skip + rowb + n);
                float2 v = make_float2((d[i][j][2 * half] + bvv + sk.x) * r2,
                                       (d[i][j][2 * half + 1] + bvv + sk.y) * r2);
                *(float2*)(Y + rowb + n) = v;
            }
        }
    }
}

// ---------------------------------------------------------------------------
// Attention, all-fp16 operands (f32 accum). CTA = (128 q, head, batch),
// 256 threads = 8 warps x 16q; each warp spans the full 64-key chunk.
//   S: f16 m16n8k16 (Q frags hoisted in registers; K fp16 [key][d] smem)
//   exp -> fp16 AV A-frags in registers (no smem round-trip)
//   AV: f16 m16n8k16 (V fp16 [d][key] smem)
// Smem (u32 units): Qs[128][36], Ks[2][64][36], Vs[2][64][36] = 55296 B.
// Double-buffered K/V; ONE __syncthreads per chunk.
// ---------------------------------------------------------------------------
__global__ __launch_bounds__(256, 2)
void attn_kernel(const float* __restrict__ Qg, const float* __restrict__ Kg,
                 const float* __restrict__ Vg, float* __restrict__ O) {
    extern __shared__ u32 dsm[];
    const u32 smb = smem_u32(dsm);
    const u32 QsA = smb;
    const u32 KsA = smb + 128 * 36 * 4;
    const u32 VsA = KsA + 2 * 64 * 36 * 4;
    const u32* Qs   = dsm;                           // [q][d_pair] stride 36
    const u32* Ksb0 = dsm + 128 * 36;                // 2 x [key][d_pair] stride 36
    const u32* Vsb0 = dsm + 128 * 36 + 2 * 64 * 36;  // 2 x [d][key_pair] stride 36

    const int tid = threadIdx.x;
    const int wid = tid >> 5, lane = tid & 31;
    const int r4 = lane >> 2, c4 = lane & 3;
    const int q0 = blockIdx.x * 128;
    const int h = blockIdx.y, b = blockIdx.z;
    const int bh = b * HEADS + h;
    const __half* Qb = (const __half*)Qg + ((size_t)bh << 16);   // [q][d]
    const __half* Kb = (const __half*)Kg + ((size_t)bh << 16);   // [key][d]
    const __half* Vb = (const __half*)Vg + ((size_t)bh << 16);   // [d][key]

    auto stageKV = [&](int ch) {
        const int kb = ch * 64;
        const u32 kd = KsA + (u32)((ch & 1) * 64 * 36 * 4);
        const u32 vd = VsA + (u32)((ch & 1) * 64 * 36 * 4);
        #pragma unroll
        for (int r = 0; r < 2; r++) {
            int idx = r * 256 + tid;
            int row = idx >> 3, c16 = idx & 7;
            cp16(kd + (u32)(row * 36 + c16 * 4) * 4, Kb + (size_t)(kb + row) * 64 + c16 * 8);
            cp16(vd + (u32)(row * 36 + c16 * 4) * 4, Vb + (size_t)row * HW + kb + c16 * 8);
        }
        CP_COMMIT();
    };

    // prologue: Q (once) + chunk 0 K/V as one group
    #pragma unroll
    for (int r = 0; r < 4; r++) {
        int idx = r * 256 + tid;
        int row = idx >> 3, c16 = idx & 7;
        cp16(QsA + (u32)(row * 36 + c16 * 4) * 4, Qb + (size_t)(q0 + row) * 64 + c16 * 8);
    }
    #pragma unroll
    for (int r = 0; r < 2; r++) {
        int idx = r * 256 + tid;
        int row = idx >> 3, c16 = idx & 7;
        cp16(KsA + (u32)(row * 36 + c16 * 4) * 4, Kb + (size_t)row * 64 + c16 * 8);
        cp16(VsA + (u32)(row * 36 + c16 * 4) * 4, Vb + (size_t)row * HW + c16 * 8);
    }
    CP_COMMIT();

    float o[8][4];
    #pragma unroll
    for (int j = 0; j < 8; j++)
        #pragma unroll
        for (int e = 0; e < 4; e++) o[j][e] = 0.f;
    float l0 = 0.f, l1 = 0.f;

    u32 aq[4][4];   // Q fragments, hoisted across all chunks

    for (int ch = 0; ch < 16; ch++) {
        CP_WAIT0();             // chunk ch landed (thread-local)
        __syncthreads();        // visible to all; all warps done with prior chunk
        if (ch == 0) {
            // hoist Q fragments (per-warp 16 q-rows x full d=64)
            const u32* qb = Qs + (wid * 16) * 36;
            #pragma unroll
            for (int t = 0; t < 4; t++) {
                aq[t][0] = qb[r4 * 36 + 8 * t + c4];
                aq[t][1] = qb[(r4 + 8) * 36 + 8 * t + c4];
                aq[t][2] = qb[r4 * 36 + 8 * t + c4 + 4];
                aq[t][3] = qb[(r4 + 8) * 36 + 8 * t + c4 + 4];
            }
        }
        if (ch < 15) stageKV(ch + 1);   // flies during this chunk's compute

        const u32* Ks = Ksb0 + (ch & 1) * 64 * 36;
        const u32* Vs = Vsb0 + (ch & 1) * 64 * 36;

        // ---- S = Q @ K^T (f16, warp = 16q x 64key, 4 k16-steps) ----
        float s[8][4];
        #pragma unroll
        for (int j = 0; j < 8; j++)
            #pragma unroll
            for (int e = 0; e < 4; e++) s[j][e] = 0.f;
        #pragma unroll
        for (int t = 0; t < 4; t++) {
            #pragma unroll
            for (int j = 0; j < 8; j++) {
                const u32* p = Ks + (8 * j + r4) * 36 + 8 * t;
                mma_f16(s[j], aq[t], p[c4], p[c4 + 4]);
            }
        }

        // ---- exp -> fp16 AV A-fragments (registers; no smem, no shuffle) ----
        u32 af[4][4];
        #pragma unroll
        for (int t = 0; t < 4; t++) {
            float e0a = __expf(s[2 * t][0]),     e1a = __expf(s[2 * t][1]);
            float e2a = __expf(s[2 * t][2]),     e3a = __expf(s[2 * t][3]);
            float e0b = __expf(s[2 * t + 1][0]), e1b = __expf(s[2 * t + 1][1]);
            float e2b = __expf(s[2 * t + 1][2]), e3b = __expf(s[2 * t + 1][3]);
            l0 += (e0a + e1a) + (e0b + e1b);
            l1 += (e2a + e3a) + (e2b + e3b);
            af[t][0] = pack_f16(e0a, e1a);
            af[t][1] = pack_f16(e2a, e3a);
            af[t][2] = pack_f16(e0b, e1b);
            af[t][3] = pack_f16(e2b, e3b);
        }

        // ---- O += P @ V (f16; B from Vs [d][key_pair] s36) ----
        #pragma unroll
        for (int t = 0; t < 4; t++) {
            #pragma unroll
            for (int j = 0; j < 8; j++) {
                const u32* p = Vs + (8 * j + r4) * 36 + t * 8;
                mma_f16(o[j], af[t], p[c4], p[c4 + 4]);
            }
        }
    }

    // ---- l reduction within 4-lane groups (warp owns its q rows) ----
    l0 += __shfl_xor_sync(0xffffffffu, l0, 1);
    l0 += __shfl_xor_sync(0xffffffffu, l0, 2);
    l1 += __shfl_xor_sync(0xffffffffu, l1, 1);
    l1 += __shfl_xor_sync(0xffffffffu, l1, 2);
    const float inv0 = 1.f / l0, inv1 = 1.f / l1;

    // ---- O / l -> [b][c][q], tf32-rounded (feeds final projection) ----
    const int qrow = q0 + wid * 16 + r4;
    #pragma unroll
    for (int j = 0; j < 8; j++) {
        const int c = h * 64 + 8 * j + 2 * c4;
        const size_t base = ((size_t)(b * DIM + c)) * HW + qrow;
        O[base]          = rndf(o[j][0] * inv0);
        O[base + HW]     = rndf(o[j][1] * inv0);
        O[base + 8]      = rndf(o[j][2] * inv1);
        O[base + HW + 8] = rndf(o[j][3] * inv1);
    }
}

// ---------------------------------------------------------------------------
// kernel_launch
// inputs: a, b, Wq, bq, Wk, bk, Wv, bv, Wp, bp, gnA_w, gnA_b, gnB_w, gnB_b
// ---------------------------------------------------------------------------
extern "C" void kernel_launch(void* const* d_in, const int* in_sizes, int n_in,
                              void* d_out, int out_size) {
    (void)in_sizes; (void)n_in; (void)out_size;
    const float* a    = (const float*)d_in[0];
    const float* bIn  = (const float*)d_in[1];
    const float* Wq   = (const float*)d_in[2];
    const float* bq   = (const float*)d_in[3];
    const float* Wk   = (const float*)d_in[4];
    const float* bk   = (const float*)d_in[5];
    const float* Wv   = (const float*)d_in[6];
    const float* bv   = (const float*)d_in[7];
    const float* Wp   = (const float*)d_in[8];
    const float* bp   = (const float*)d_in[9];
    const float* gnAw = (const float*)d_in[10];
    const float* gnAb = (const float*)d_in[11];
    const float* gnBw = (const float*)d_in[12];
    const float* gnBb = (const float*)d_in[13];
    float* out = (float*)d_out;

    float *an, *bn, *q, *k, *v, *hb, *wbuf;
    cudaGetSymbolAddress((void**)&an, g_an);
    cudaGetSymbolAddress((void**)&bn, g_bn);
    cudaGetSymbolAddress((void**)&q,  g_q);
    cudaGetSymbolAddress((void**)&k,  g_k);
    cudaGetSymbolAddress((void**)&v,  g_v);
    cudaGetSymbolAddress((void**)&hb, g_h);
    cudaGetSymbolAddress((void**)&wbuf, g_w);

    const int PROJ_SMEM = (2 * 128 * 40 + 2 * 32 * 136) * 4;           // 75776 B
    const int ATTN_SMEM = (128 * 36 + 2 * 64 * 36 + 2 * 64 * 36) * 4;  // 55296 B
    cudaFuncSetAttribute((const void*)qkv_kernel,   cudaFuncAttributeMaxDynamicSharedMemorySize, PROJ_SMEM);
    cudaFuncSetAttribute((const void*)final_kernel, cudaFuncAttributeMaxDynamicSharedMemorySize, PROJ_SMEM);
    cudaFuncSetAttribute((const void*)attn_kernel,  cudaFuncAttributeMaxDynamicSharedMemorySize, ATTN_SMEM);

    wconv_kernel<<<dim3(64, 4), 256>>>(Wq, Wk, Wv, Wp, wbuf);

    gn_kernel<<<dim3(32, BATCH, 2), 256>>>(a, bIn, gnAw, gnAb, gnBw, gnBb, an, bn);

    qkv_kernel<<<dim3(HW / 128, DIM / 128, 3 * BATCH), 256, PROJ_SMEM>>>(
        wbuf, an, bn, bq, bk, bv, q, k, v);

    attn_kernel<<<dim3(HW / 128, HEADS, BATCH), 256, ATTN_SMEM>>>(q, k, v, hb);

    final_kernel<<<dim3(HW / 128, DIM / 128, BATCH), 256, PROJ_SMEM>>>(
        wbuf + 3 * DIM * DIM, hb, bp, bIn, out);
}